// round 10
// baseline (speedup 1.0000x reference)
#include <cuda_runtime.h>
#include <cstdint>
#include <math.h>

#define B_IMG 8
#define NPROP 4000
#define NCLS 91
#define NCM1 90
#define CAPC 4000                    // worst-case candidates per (image,class)
#define NDET 100
#define NEGV -1e9f
#define WCAP 320                     // warp-path cap per (image,class)
#define KWORDS 10                    // ceil(WCAP/32) alive bits per lane
#define WPB 4                        // warps (tasks) per block
#define SV_PER_IMG (NCM1 * NDET)     // 9000 survivors per image (capped)
#define GCAP 1024                    // topk gather capacity
#define HBINS 2048
#define HLO 30720                    // (key>>15) offset; covers scores >~0.0078
#define NBLKA 2000                   // phaseAB blocks (16 proposals each)
#define QCAP 320                     // smem queue cap (<=20 passers/proposal)
#define FULLM 0xffffffffu

static __device__ float4        g_cbox[B_IMG * NCM1 * CAPC];
static __device__ float         g_cs[B_IMG * NCM1 * CAPC];
static __device__ int           g_ccnt[B_IMG * NCM1];    // zero-init, self-reset
static __device__ float4        g_svbox[B_IMG * SV_PER_IMG];
static __device__ float         g_svsc[B_IMG * SV_PER_IMG];
static __device__ unsigned char g_svlab[B_IMG * SV_PER_IMG];
static __device__ int           g_svcnt[B_IMG];          // zero-init, self-reset
static __device__ int           g_hist[B_IMG * HBINS];   // zero-init, topk re-zeros

__device__ __forceinline__ float load_dim(const int* p) {
    int vi = *p;
    if (vi > 0 && vi < 1000000) return (float)vi;
    return __int_as_float(vi);
}

__device__ __forceinline__ int score_bkt(unsigned keybits) {
    int bkt = (int)(keybits >> 15) - HLO;
    return max(0, min(HBINS - 1, bkt));
}

// ---------------------------------------------------------------------------
// Phase AB (fused): softmax + threshold filter -> smem queue -> dense decode.
// ---------------------------------------------------------------------------
__global__ void __launch_bounds__(256)
phaseAB_kernel(const float* __restrict__ logits,
               const float* __restrict__ reg,
               const float* __restrict__ props,
               const int* __restrict__ ph,
               const int* __restrict__ pw) {
    const int warp = threadIdx.x >> 5;
    const int lane = threadIdx.x & 31;
    const int p0 = (blockIdx.x * 8 + warp) << 1;

    __shared__ unsigned long long q[QCAP];
    __shared__ int s_cnt;
    if (threadIdx.x == 0) s_cnt = 0;
    __syncthreads();

    const float* z0 = logits + (size_t)p0 * NCLS;
    const float* z1 = z0 + NCLS;

    float e[2][3];
    e[0][0] = __expf(z0[lane]);
    e[1][0] = __expf(z1[lane]);
    e[0][1] = __expf(z0[lane + 32]);
    e[1][1] = __expf(z1[lane + 32]);
    e[0][2] = (lane < NCLS - 64) ? __expf(z0[lane + 64]) : 0.0f;
    e[1][2] = (lane < NCLS - 64) ? __expf(z1[lane + 64]) : 0.0f;

    float ssum[2];
    ssum[0] = e[0][0] + e[0][1] + e[0][2];
    ssum[1] = e[1][0] + e[1][1] + e[1][2];
    #pragma unroll
    for (int o = 16; o; o >>= 1) {
        ssum[0] += __shfl_xor_sync(FULLM, ssum[0], o);
        ssum[1] += __shfl_xor_sync(FULLM, ssum[1], o);
    }

    bool pass[6];
    int cnt = 0;
    #pragma unroll
    for (int k = 0; k < 2; k++) {
        float thr = 0.05f * ssum[k];
        #pragma unroll
        for (int t = 0; t < 3; t++) {
            int c = lane + 32 * t;
            bool pk = (c > 0) && (c < NCLS) && (e[k][t] > thr);
            pass[k * 3 + t] = pk;
            cnt += pk ? 1 : 0;
        }
    }

    int incl = cnt;
    #pragma unroll
    for (int o = 1; o < 32; o <<= 1) {
        int v = __shfl_up_sync(FULLM, incl, o);
        if (lane >= o) incl += v;
    }
    int total = __shfl_sync(FULLM, incl, 31);
    int wbase = 0;
    if (total > 0) {
        if (lane == 31) wbase = atomicAdd(&s_cnt, total);
        wbase = __shfl_sync(FULLM, wbase, 31);
        int off = wbase + incl - cnt;
        #pragma unroll
        for (int k = 0; k < 2; k++) {
            #pragma unroll
            for (int t = 0; t < 3; t++) {
                if (pass[k * 3 + t]) {
                    int c = lane + 32 * t;
                    float sc = e[k][t] / ssum[k];
                    unsigned idx = ((unsigned)(p0 + k) << 7) | (unsigned)c;
                    q[off++] = ((unsigned long long)__float_as_uint(sc) << 32) | idx;
                }
            }
        }
    }
    __syncthreads();

    const int qcnt = s_cnt;
    const float Wf = load_dim(pw);
    const float Hf = load_dim(ph);
    const float CLIPV = 4.135166556742356f;  // log(1000/16)

    for (int i = threadIdx.x; i < qcnt; i += 256) {
        unsigned long long en = q[i];
        float sc = __uint_as_float((unsigned)(en >> 32));
        unsigned idx = (unsigned)en;
        int p = idx >> 7, c = idx & 127;

        float4 pr = ((const float4*)props)[p];
        float w = pr.z - pr.x, h = pr.w - pr.y;
        float cx = pr.x + 0.5f * w, cy = pr.y + 0.5f * h;
        float4 r = ((const float4*)reg)[p * NCLS + c];

        float dx = r.x / 10.0f, dy = r.y / 10.0f;
        float dw = fminf(r.z / 5.0f, CLIPV);
        float dh = fminf(r.w / 5.0f, CLIPV);
        float pcx = dx * w + cx, pcy = dy * h + cy;
        float pwd = __expf(dw) * w, phd = __expf(dh) * h;
        float x1 = pcx - 0.5f * pwd, y1 = pcy - 0.5f * phd;
        float x2 = pcx + 0.5f * pwd, y2 = pcy + 0.5f * phd;
        x1 = fminf(fmaxf(x1, 0.0f), Wf); x2 = fminf(fmaxf(x2, 0.0f), Wf);
        y1 = fminf(fmaxf(y1, 0.0f), Hf); y2 = fminf(fmaxf(y2, 0.0f), Hf);
        if ((x2 - x1) >= 0.01f && (y2 - y1) >= 0.01f) {
            int b = p / NPROP;
            int bc = b * NCM1 + (c - 1);
            int pos = atomicAdd(&g_ccnt[bc], 1);
            size_t o = (size_t)bc * CAPC + pos;
            g_cbox[o] = make_float4(x1, y1, x2, y2);
            g_cs[o]   = sc;
        }
    }
}

// ---------------------------------------------------------------------------
// Phase B: ONE WARP per (image,class) task. Rank sort into smem, then lazy
// greedy NMS: alive bits in registers (lane L owns j == L mod 32), IoU only
// vs selected survivors. No __syncthreads; 720 warps run in one wave.
// ---------------------------------------------------------------------------
__global__ void __launch_bounds__(32 * WPB)
class_nms_kernel(void) {
    const int task = blockIdx.x * WPB + (threadIdx.x >> 5);
    const int lane = threadIdx.x & 31;
    const int warp = threadIdx.x >> 5;
    const int b  = task / NCM1;
    const int c  = (task % NCM1) + 1;
    const int bc = task;
    const int n  = g_ccnt[bc];
    if (n == 0) return;

    __shared__ unsigned long long skey[WPB][WCAP];
    __shared__ unsigned long long ssort[WPB][WCAP];
    __shared__ float4             sbox[WPB][WCAP];
    __shared__ unsigned short     surv[WPB][NDET];

    const size_t base = (size_t)bc * CAPC;
    unsigned long long* skeyW  = skey[warp];
    unsigned long long* ssortW = ssort[warp];
    float4*             sboxW  = sbox[warp];
    unsigned short*     survW  = surv[warp];

    if (n <= WCAP) {
        // ---- warp fast path ----
        for (int j = lane; j < n; j += 32)
            skeyW[j] = ((unsigned long long)__float_as_uint(g_cs[base + j]) << 32)
                     | (unsigned)j;
        __syncwarp();
        for (int i = lane; i < n; i += 32) {
            unsigned long long ki = skeyW[i];
            int r = 0;
            for (int j = 0; j < n; j++) r += (skeyW[j] > ki);
            ssortW[r] = ki;
        }
        __syncwarp();
        for (int i = lane; i < n; i += 32)
            sboxW[i] = g_cbox[base + (unsigned)(ssortW[i] & 0xffffffffu)];
        __syncwarp();

        // alive bits: bit k of am <-> j = k*32 + lane
        unsigned am = 0;
        #pragma unroll
        for (int k = 0; k < KWORDS; k++)
            if (k * 32 + lane < n) am |= 1u << k;

        int ns = 0;
        for (int i = 0; i < n && ns < NDET; i++) {
            unsigned ami = __shfl_sync(FULLM, am, i & 31);
            if (!((ami >> (i >> 5)) & 1u)) continue;
            if (lane == 0) survW[ns] = (unsigned short)i;
            ns++;
            float4 bi = sboxW[i];
            float ai = (bi.z - bi.x) * (bi.w - bi.y);
            #pragma unroll
            for (int k = 0; k < KWORDS; k++) {
                if (!(am & (1u << k))) continue;
                int j = k * 32 + lane;
                // j<i alive => survivor with IoU<=0.5 vs i (else i dead): no-op.
                // j==i: self-IoU clears own bit; i never revisited: harmless.
                float4 bj = sboxW[j];
                float ix1 = fmaxf(bi.x, bj.x), iy1 = fmaxf(bi.y, bj.y);
                float ix2 = fminf(bi.z, bj.z), iy2 = fminf(bi.w, bj.w);
                float inter = fmaxf(ix2 - ix1, 0.0f) * fmaxf(iy2 - iy1, 0.0f);
                float aj = (bj.z - bj.x) * (bj.w - bj.y);
                if (inter > 0.5f * (ai + aj - inter)) am &= ~(1u << k);
            }
        }
        __syncwarp();

        int sbase = 0;
        if (lane == 0) sbase = atomicAdd(&g_svcnt[b], ns);
        sbase = __shfl_sync(FULLM, sbase, 0);
        const int so = b * SV_PER_IMG + sbase;
        for (int s = lane; s < ns; s += 32) {
            int i = survW[s];
            unsigned kb = (unsigned)(ssortW[i] >> 32);
            g_svbox[so + s] = sboxW[i];
            g_svsc[so + s]  = __uint_as_float(kb);
            g_svlab[so + s] = (unsigned char)c;
            atomicAdd(&g_hist[b * HBINS + score_bkt(kb)], 1);
        }
    } else {
        // ---- warp-serial global fallback (n > 320; essentially never) ----
        for (int it = 0; it < NDET; it++) {
            float bv = -2e9f; int bi = 0x7fffffff;
            for (int j = lane; j < n; j += 32) {
                float v = g_cs[base + j];
                if (v > bv || (v == bv && j < bi)) { bv = v; bi = j; }
            }
            #pragma unroll
            for (int o = 16; o; o >>= 1) {
                float ov = __shfl_xor_sync(FULLM, bv, o);
                int   oi = __shfl_xor_sync(FULLM, bi, o);
                if (ov > bv || (ov == bv && oi < bi)) { bv = ov; bi = oi; }
            }
            if (bv < -5e8f) break;
            float4 bx = g_cbox[base + bi];
            float ai = (bx.z - bx.x) * (bx.w - bx.y);
            for (int j = lane; j < n; j += 32) {
                float v = g_cs[base + j];
                if (v < -5e8f) continue;
                float4 bj = g_cbox[base + j];
                float ix1 = fmaxf(bx.x, bj.x), iy1 = fmaxf(bx.y, bj.y);
                float ix2 = fminf(bx.z, bj.z), iy2 = fminf(bx.w, bj.w);
                float inter = fmaxf(ix2 - ix1, 0.0f) * fmaxf(iy2 - iy1, 0.0f);
                float aj = (bj.z - bj.x) * (bj.w - bj.y);
                if (inter > 0.5f * (ai + aj - inter)) g_cs[base + j] = NEGV;
            }
            __syncwarp();
            if (lane == 0) {
                g_cs[base + bi] = NEGV;
                int slot = atomicAdd(&g_svcnt[b], 1);
                g_svbox[b * SV_PER_IMG + slot] = bx;
                g_svsc[b * SV_PER_IMG + slot]  = bv;
                g_svlab[b * SV_PER_IMG + slot] = (unsigned char)c;
                atomicAdd(&g_hist[b * HBINS + score_bkt(__float_as_uint(bv))], 1);
            }
            __syncwarp();
        }
    }
    __syncwarp();
    if (lane == 0) g_ccnt[bc] = 0;   // self-reset for next graph replay
}

// ---------------------------------------------------------------------------
// Phase C: one block per image. Precomputed histogram -> suffix sum -> pivot
// -> gather -> rank sort -> emit. Re-zeros g_hist.
// ---------------------------------------------------------------------------
__global__ void __launch_bounds__(1024)
topk_kernel(float* __restrict__ out) {
    const int b   = blockIdx.x;
    const int tid = threadIdx.x;
    const int wid = tid >> 5;
    const int lane = tid & 31;
    const int n   = g_svcnt[b];
    const int base = b * SV_PER_IMG;
    const int nsel = (n < NDET) ? n : NDET;

    __shared__ int hist[HBINS];
    __shared__ int chunksum[32];
    __shared__ int chunksuf[32];
    __shared__ unsigned long long keys[GCAP];
    __shared__ unsigned long long skeys[GCAP];
    __shared__ int gcnt_s, pb_s;

    for (int i = tid; i < HBINS; i += 1024) {
        hist[i] = g_hist[b * HBINS + i];
        g_hist[b * HBINS + i] = 0;
    }
    if (tid == 0) { gcnt_s = 0; pb_s = 0; }
    __syncthreads();

    int h0 = hist[(wid << 6) + (lane << 1)];
    int h1 = hist[(wid << 6) + (lane << 1) + 1];
    int acc = h0 + h1;
    #pragma unroll
    for (int o = 1; o < 32; o <<= 1) {
        int v = __shfl_down_sync(FULLM, acc, o);
        if (lane + o < 32) acc += v;
    }
    if (lane == 0) chunksum[wid] = acc;
    __syncthreads();
    if (wid == 0) {
        int cs = chunksum[lane];
        int a2 = cs;
        #pragma unroll
        for (int o = 1; o < 32; o <<= 1) {
            int v = __shfl_down_sync(FULLM, a2, o);
            if (lane + o < 32) a2 += v;
        }
        chunksuf[lane] = a2 - cs;
    }
    __syncthreads();
    {
        int above = chunksuf[wid];
        hist[(wid << 6) + (lane << 1)]     = above + acc;
        hist[(wid << 6) + (lane << 1) + 1] = above + acc - h0;
    }
    __syncthreads();

    if (nsel > 0) {
        for (int i = tid; i < HBINS; i += 1024) {
            int s = hist[i];
            int sn = (i + 1 < HBINS) ? hist[i + 1] : 0;
            if (s >= nsel && sn < nsel) pb_s = i;
        }
    }
    __syncthreads();
    const int pb = pb_s;
    const int m  = (nsel > 0) ? hist[pb] : 0;

    if (m <= GCAP) {
        for (int j = tid; j < n; j += 1024) {
            unsigned k = __float_as_uint(g_svsc[base + j]);
            if (score_bkt(k) >= pb) {
                int slot = atomicAdd(&gcnt_s, 1);
                keys[slot] = ((unsigned long long)k << 32) | (unsigned)(~j);
            }
        }
        __syncthreads();
        for (int i = tid; i < m; i += 1024) {
            unsigned long long ki = keys[i];
            int r = 0;
            for (int j = 0; j < m; j++) r += (keys[j] > ki);
            skeys[r] = ki;
        }
        __syncthreads();
    } else {
        __shared__ float red_v[32];
        __shared__ int   red_i[32];
        for (int it = 0; it < nsel; it++) {
            float bv = -2e9f; int bi = 0;
            for (int j = tid; j < n; j += 1024) {
                float v = g_svsc[base + j];
                if (v > bv) { bv = v; bi = j; }
            }
            #pragma unroll
            for (int o = 16; o; o >>= 1) {
                float ov = __shfl_xor_sync(FULLM, bv, o);
                int   oi = __shfl_xor_sync(FULLM, bi, o);
                if (ov > bv || (ov == bv && oi < bi)) { bv = ov; bi = oi; }
            }
            if ((tid & 31) == 0) { red_v[tid >> 5] = bv; red_i[tid >> 5] = bi; }
            __syncthreads();
            if (tid == 0) {
                for (int wv = 1; wv < 32; wv++)
                    if (red_v[wv] > red_v[0] ||
                        (red_v[wv] == red_v[0] && red_i[wv] < red_i[0])) {
                        red_v[0] = red_v[wv]; red_i[0] = red_i[wv];
                    }
                int bsel = red_i[0];
                skeys[it] = ((unsigned long long)__float_as_uint(red_v[0]) << 32)
                          | (unsigned)(~bsel);
                g_svsc[base + bsel] = NEGV;
            }
            __syncthreads();
        }
    }

    // emit: [boxes 8*100*4][scores 8*100][labels 8*100][keep 8*100]
    const int SC0 = B_IMG * NDET * 4;
    const int LB0 = SC0 + B_IMG * NDET;
    const int KP0 = LB0 + B_IMG * NDET;
    for (int i = tid; i < NDET; i += 1024) {
        float4 bx = make_float4(0.f, 0.f, 0.f, 0.f);
        float sc = 0.0f, lb = 0.0f, kp = 0.0f;
        if (i < nsel) {
            unsigned long long kk = skeys[i];
            int j = (int)(~(unsigned)kk);
            bx = g_svbox[base + j];
            sc = __uint_as_float((unsigned)(kk >> 32));
            lb = (float)g_svlab[base + j];
            kp = 1.0f;
        }
        float* ob = out + ((size_t)b * NDET + i) * 4;
        ob[0] = bx.x; ob[1] = bx.y; ob[2] = bx.z; ob[3] = bx.w;
        out[SC0 + b * NDET + i] = sc;
        out[LB0 + b * NDET + i] = lb;
        out[KP0 + b * NDET + i] = kp;
    }
    if (tid == 0) g_svcnt[b] = 0;   // self-reset for next graph replay
}

extern "C" void kernel_launch(void* const* d_in, const int* in_sizes, int n_in,
                              void* d_out, int out_size) {
    const float* logits = (const float*)d_in[0];
    const float* reg    = (const float*)d_in[1];
    const float* props  = (const float*)d_in[2];
    const int*   ih     = (const int*)d_in[3];
    const int*   iw     = (const int*)d_in[4];
    float* out = (float*)d_out;

    phaseAB_kernel<<<NBLKA, 256>>>(logits, reg, props, ih, iw);
    class_nms_kernel<<<(B_IMG * NCM1) / WPB, 32 * WPB>>>();
    topk_kernel<<<B_IMG, 1024>>>(out);
}

// round 11
// speedup vs baseline: 1.0221x; 1.0221x over previous
#include <cuda_runtime.h>
#include <cstdint>
#include <math.h>

#define B_IMG 8
#define NPROP 4000
#define NCLS 91
#define NCM1 90
#define CAPC 4000                    // worst-case candidates per (image,class)
#define NDET 100
#define NEGV -1e9f
#define CAPSM 512                    // smem sort cap for class NMS
#define MASKN 320                    // mask-path cap (NW <= 5)
#define NWM 5                        // mask words per row
#define SV_PER_IMG (NCM1 * NDET)     // 9000 survivors per image (capped)
#define GCAP2 512                    // topk gather capacity
#define HBINS 2048
#define HLO 30720                    // (key>>15) offset; covers scores >~0.0078
#define NBLKA 2000                   // phaseAB blocks (16 proposals each)
#define QCAP 320                     // smem queue cap (<=20 passers/proposal)
#define FULLM 0xffffffffu

static __device__ float4        g_cbox[B_IMG * NCM1 * CAPC];
static __device__ float         g_cs[B_IMG * NCM1 * CAPC];
static __device__ int           g_ccnt[B_IMG * NCM1];    // zero-init, self-reset
static __device__ float4        g_svbox[B_IMG * SV_PER_IMG];
static __device__ float         g_svsc[B_IMG * SV_PER_IMG];
static __device__ unsigned char g_svlab[B_IMG * SV_PER_IMG];
static __device__ int           g_svcnt[B_IMG];          // zero-init, self-reset
static __device__ int           g_hist[B_IMG * HBINS];   // zero-init, self-reset
static __device__ int           g_done[B_IMG];           // zero-init, self-reset

__device__ __forceinline__ float load_dim(const int* p) {
    int vi = *p;
    if (vi > 0 && vi < 1000000) return (float)vi;
    return __int_as_float(vi);
}

__device__ __forceinline__ int score_bkt(unsigned keybits) {
    int bkt = (int)(keybits >> 15) - HLO;
    return max(0, min(HBINS - 1, bkt));
}

// ---------------------------------------------------------------------------
// Phase AB (fused): softmax + threshold filter -> smem queue -> dense decode.
// (unchanged from R9 — measured 19.3us)
// ---------------------------------------------------------------------------
__global__ void __launch_bounds__(256)
phaseAB_kernel(const float* __restrict__ logits,
               const float* __restrict__ reg,
               const float* __restrict__ props,
               const int* __restrict__ ph,
               const int* __restrict__ pw) {
    const int warp = threadIdx.x >> 5;
    const int lane = threadIdx.x & 31;
    const int p0 = (blockIdx.x * 8 + warp) << 1;

    __shared__ unsigned long long q[QCAP];
    __shared__ int s_cnt;
    if (threadIdx.x == 0) s_cnt = 0;
    __syncthreads();

    const float* z0 = logits + (size_t)p0 * NCLS;
    const float* z1 = z0 + NCLS;

    float e[2][3];
    e[0][0] = __expf(z0[lane]);
    e[1][0] = __expf(z1[lane]);
    e[0][1] = __expf(z0[lane + 32]);
    e[1][1] = __expf(z1[lane + 32]);
    e[0][2] = (lane < NCLS - 64) ? __expf(z0[lane + 64]) : 0.0f;
    e[1][2] = (lane < NCLS - 64) ? __expf(z1[lane + 64]) : 0.0f;

    float ssum[2];
    ssum[0] = e[0][0] + e[0][1] + e[0][2];
    ssum[1] = e[1][0] + e[1][1] + e[1][2];
    #pragma unroll
    for (int o = 16; o; o >>= 1) {
        ssum[0] += __shfl_xor_sync(FULLM, ssum[0], o);
        ssum[1] += __shfl_xor_sync(FULLM, ssum[1], o);
    }

    bool pass[6];
    int cnt = 0;
    #pragma unroll
    for (int k = 0; k < 2; k++) {
        float thr = 0.05f * ssum[k];
        #pragma unroll
        for (int t = 0; t < 3; t++) {
            int c = lane + 32 * t;
            bool pk = (c > 0) && (c < NCLS) && (e[k][t] > thr);
            pass[k * 3 + t] = pk;
            cnt += pk ? 1 : 0;
        }
    }

    int incl = cnt;
    #pragma unroll
    for (int o = 1; o < 32; o <<= 1) {
        int v = __shfl_up_sync(FULLM, incl, o);
        if (lane >= o) incl += v;
    }
    int total = __shfl_sync(FULLM, incl, 31);
    int wbase = 0;
    if (total > 0) {
        if (lane == 31) wbase = atomicAdd(&s_cnt, total);
        wbase = __shfl_sync(FULLM, wbase, 31);
        int off = wbase + incl - cnt;
        #pragma unroll
        for (int k = 0; k < 2; k++) {
            #pragma unroll
            for (int t = 0; t < 3; t++) {
                if (pass[k * 3 + t]) {
                    int c = lane + 32 * t;
                    float sc = e[k][t] / ssum[k];
                    unsigned idx = ((unsigned)(p0 + k) << 7) | (unsigned)c;
                    q[off++] = ((unsigned long long)__float_as_uint(sc) << 32) | idx;
                }
            }
        }
    }
    __syncthreads();

    const int qcnt = s_cnt;
    const float Wf = load_dim(pw);
    const float Hf = load_dim(ph);
    const float CLIPV = 4.135166556742356f;  // log(1000/16)

    for (int i = threadIdx.x; i < qcnt; i += 256) {
        unsigned long long en = q[i];
        float sc = __uint_as_float((unsigned)(en >> 32));
        unsigned idx = (unsigned)en;
        int p = idx >> 7, c = idx & 127;

        float4 pr = ((const float4*)props)[p];
        float w = pr.z - pr.x, h = pr.w - pr.y;
        float cx = pr.x + 0.5f * w, cy = pr.y + 0.5f * h;
        float4 r = ((const float4*)reg)[p * NCLS + c];

        float dx = r.x / 10.0f, dy = r.y / 10.0f;
        float dw = fminf(r.z / 5.0f, CLIPV);
        float dh = fminf(r.w / 5.0f, CLIPV);
        float pcx = dx * w + cx, pcy = dy * h + cy;
        float pwd = __expf(dw) * w, phd = __expf(dh) * h;
        float x1 = pcx - 0.5f * pwd, y1 = pcy - 0.5f * phd;
        float x2 = pcx + 0.5f * pwd, y2 = pcy + 0.5f * phd;
        x1 = fminf(fmaxf(x1, 0.0f), Wf); x2 = fminf(fmaxf(x2, 0.0f), Wf);
        y1 = fminf(fmaxf(y1, 0.0f), Hf); y2 = fminf(fmaxf(y2, 0.0f), Hf);
        if ((x2 - x1) >= 0.01f && (y2 - y1) >= 0.01f) {
            int b = p / NPROP;
            int bc = b * NCM1 + (c - 1);
            int pos = atomicAdd(&g_ccnt[bc], 1);
            size_t o = (size_t)bc * CAPC + pos;
            g_cbox[o] = make_float4(x1, y1, x2, y2);
            g_cs[o]   = sc;
        }
    }
}

// ---------------------------------------------------------------------------
// Fused NMS + topk: one block per (image,class) does R9's block NMS; the
// LAST-finished block of each image (g_done release/acquire) runs the
// radix-select top-100 inline. Smem union: topk reuses the dead NMS buffers.
// ---------------------------------------------------------------------------
struct NmsSm {
    unsigned long long skey[CAPSM];          // 4KB
    unsigned long long ssort[CAPSM];         // 4KB
    float4             sbox[CAPSM];          // 8KB
    unsigned long long mask[MASKN * NWM];    // 12.5KB
    unsigned char      alive[CAPSM];         // 0.5KB
};
struct TopkSm {
    int                hist[HBINS];          // 8KB
    unsigned long long keys[GCAP2];          // 4KB
    unsigned long long skeys[GCAP2];         // 4KB
    int                warpsum[8];
    int                warp_above[8];
};
union SmU { NmsSm nms; TopkSm tk; };

__global__ void __launch_bounds__(256)
nms_topk_kernel(float* __restrict__ out,
                const int* __restrict__ ph, const int* __restrict__ pw) {
    const int c  = blockIdx.x + 1;
    const int b  = blockIdx.y;
    const int bc = b * NCM1 + (c - 1);
    const int tid = threadIdx.x;
    const int wid = tid >> 5;
    const int lane = tid & 31;
    const int n = g_ccnt[bc];

    __shared__ SmU sm;
    __shared__ unsigned short surv[NDET];
    __shared__ float          survsc[NDET];
    __shared__ int            nsurv_s, sbase_s, lastf;
    __shared__ float          red_v[8];
    __shared__ int            red_i[8];
    __shared__ int            stop_s, seli_s, gcnt_s, pb_s;
    __shared__ float4         selbox_s;
    __shared__ float          gsc_s;

    const size_t base = (size_t)bc * CAPC;

    // =================== NMS phase (R9 block version) ===================
    if (n > 0 && n <= CAPSM) {
        for (int j = tid; j < n; j += 256)
            sm.nms.skey[j] =
                ((unsigned long long)__float_as_uint(g_cs[base + j]) << 32)
              | (unsigned)j;
        __syncthreads();
        for (int i = tid; i < n; i += 256) {
            unsigned long long ki = sm.nms.skey[i];
            int r = 0;
            for (int j = 0; j < n; j++) r += (sm.nms.skey[j] > ki);
            sm.nms.ssort[r] = ki;
        }
        __syncthreads();
        for (int i = tid; i < n; i += 256)
            sm.nms.sbox[i] = g_cbox[base + (unsigned)(sm.nms.ssort[i] & 0xffffffffu)];

        if (n <= MASKN) {
            __syncthreads();
            const int NW = (n + 63) >> 6;
            for (int idx = tid; idx < n * NW; idx += 256) {
                int i = idx / NW, w = idx - i * NW;
                unsigned long long bits = 0ull;
                int j0 = w << 6;
                int jend = min(n, j0 + 64);
                int jbeg = max(j0, i + 1);
                if (jbeg < jend) {
                    float4 bi = sm.nms.sbox[i];
                    float ai = (bi.z - bi.x) * (bi.w - bi.y);
                    for (int j = jbeg; j < jend; j++) {
                        float4 bj = sm.nms.sbox[j];
                        float ix1 = fmaxf(bi.x, bj.x), iy1 = fmaxf(bi.y, bj.y);
                        float ix2 = fminf(bi.z, bj.z), iy2 = fminf(bi.w, bj.w);
                        float inter = fmaxf(ix2 - ix1, 0.0f) * fmaxf(iy2 - iy1, 0.0f);
                        float aj = (bj.z - bj.x) * (bj.w - bj.y);
                        if (inter > 0.5f * (ai + aj - inter))
                            bits |= 1ull << (j - j0);
                    }
                }
                sm.nms.mask[i * NWM + w] = bits;
            }
            __syncthreads();
            if (tid == 0) {
                unsigned long long dead[NWM];
                #pragma unroll
                for (int w = 0; w < NWM; w++) dead[w] = 0ull;
                int ns = 0;
                for (int i = 0; i < n && ns < NDET; i++) {
                    if ((dead[i >> 6] >> (i & 63)) & 1ull) continue;
                    surv[ns] = (unsigned short)i;
                    survsc[ns] = __uint_as_float((unsigned)(sm.nms.ssort[i] >> 32));
                    ns++;
                    for (int w = i >> 6; w < NW; w++)
                        dead[w] |= sm.nms.mask[i * NWM + w];
                }
                nsurv_s = ns;
                sbase_s = atomicAdd(&g_svcnt[b], ns);
            }
        } else {
            for (int i = tid; i < n; i += 256) sm.nms.alive[i] = 1;
            __syncthreads();
            if (tid < 32) {
                int ns = 0;
                for (int i = 0; i < n && ns < NDET; i++) {
                    if (sm.nms.alive[i] == 0) continue;
                    if (tid == 0) {
                        surv[ns] = (unsigned short)i;
                        survsc[ns] = __uint_as_float((unsigned)(sm.nms.ssort[i] >> 32));
                    }
                    ns++;
                    float4 bi = sm.nms.sbox[i];
                    float ai = (bi.z - bi.x) * (bi.w - bi.y);
                    for (int j = i + 1 + tid; j < n; j += 32) {
                        if (!sm.nms.alive[j]) continue;
                        float4 bj = sm.nms.sbox[j];
                        float ix1 = fmaxf(bi.x, bj.x), iy1 = fmaxf(bi.y, bj.y);
                        float ix2 = fminf(bi.z, bj.z), iy2 = fminf(bi.w, bj.w);
                        float inter = fmaxf(ix2 - ix1, 0.0f) * fmaxf(iy2 - iy1, 0.0f);
                        float aj = (bj.z - bj.x) * (bj.w - bj.y);
                        if (inter > 0.5f * (ai + aj - inter)) sm.nms.alive[j] = 0;
                    }
                    __syncwarp();
                }
                if (tid == 0) {
                    nsurv_s = ns;
                    sbase_s = atomicAdd(&g_svcnt[b], ns);
                }
            }
        }
        __syncthreads();
        const int so = b * SV_PER_IMG + sbase_s;
        for (int s = tid; s < nsurv_s; s += 256) {
            int i = surv[s];
            float sv = survsc[s];
            g_svbox[so + s] = sm.nms.sbox[i];
            g_svsc[so + s]  = sv;
            g_svlab[so + s] = (unsigned char)c;
            atomicAdd(&g_hist[b * HBINS + score_bkt(__float_as_uint(sv))], 1);
        }
    } else if (n > CAPSM) {
        // ---- global argmax fallback (essentially never) ----
        const float Hf = load_dim(ph);
        const float Wf = load_dim(pw);
        const float off = fmaxf(Hf, Wf) + 1.0f;
        const float t = (float)c * off;
        for (int it = 0; it < NDET; it++) {
            float bv = -2e9f; int bi = 0;
            for (int j = tid; j < n; j += 256) {
                float v = g_cs[base + j];
                if (v > bv) { bv = v; bi = j; }
            }
            #pragma unroll
            for (int o = 16; o; o >>= 1) {
                float ov = __shfl_xor_sync(FULLM, bv, o);
                int   oi = __shfl_xor_sync(FULLM, bi, o);
                if (ov > bv || (ov == bv && oi < bi)) { bv = ov; bi = oi; }
            }
            if ((tid & 31) == 0) { red_v[tid >> 5] = bv; red_i[tid >> 5] = bi; }
            __syncthreads();
            if (tid == 0) {
                for (int wv = 1; wv < 8; wv++)
                    if (red_v[wv] > red_v[0] ||
                        (red_v[wv] == red_v[0] && red_i[wv] < red_i[0])) {
                        red_v[0] = red_v[wv]; red_i[0] = red_i[wv];
                    }
                if (red_v[0] < -5e8f) stop_s = 1;
                else {
                    stop_s = 0; seli_s = red_i[0];
                    selbox_s = g_cbox[base + red_i[0]];
                    gsc_s = red_v[0];
                }
            }
            __syncthreads();
            if (stop_s) break;
            float4 bx = selbox_s;
            float ox1 = bx.x + t, oy1 = bx.y + t, ox2 = bx.z + t, oy2 = bx.w + t;
            float ai = (ox2 - ox1) * (oy2 - oy1);
            for (int j = tid; j < n; j += 256) {
                float v = g_cs[base + j];
                if (v < -5e8f) continue;
                float4 bj = g_cbox[base + j];
                float jx1 = bj.x + t, jy1 = bj.y + t, jx2 = bj.z + t, jy2 = bj.w + t;
                float ix1 = fmaxf(ox1, jx1), iy1 = fmaxf(oy1, jy1);
                float ix2 = fminf(ox2, jx2), iy2 = fminf(oy2, jy2);
                float inter = fmaxf(ix2 - ix1, 0.0f) * fmaxf(iy2 - iy1, 0.0f);
                float aj = (jx2 - jx1) * (jy2 - jy1);
                if (inter > 0.5f * (ai + aj - inter)) g_cs[base + j] = NEGV;
            }
            __syncthreads();
            if (tid == 0) {
                g_cs[base + seli_s] = NEGV;
                int slot = atomicAdd(&g_svcnt[b], 1);
                g_svbox[b * SV_PER_IMG + slot] = selbox_s;
                g_svsc[b * SV_PER_IMG + slot]  = gsc_s;
                g_svlab[b * SV_PER_IMG + slot] = (unsigned char)c;
                atomicAdd(&g_hist[b * HBINS + score_bkt(__float_as_uint(gsc_s))], 1);
            }
            __syncthreads();
        }
    }

    // ============ release-arrive on per-image done counter ============
    __threadfence();
    __syncthreads();
    if (tid == 0) {
        if (n > 0) g_ccnt[bc] = 0;                 // self-reset for replay
        lastf = (atomicAdd(&g_done[b], 1) == NCM1 - 1);
    }
    __syncthreads();
    if (!lastf) return;
    __threadfence();                               // acquire all blocks' writes

    // =================== topk phase (last block only) ===================
    const int nv = g_svcnt[b];
    const int sbase = b * SV_PER_IMG;
    const int nsel = (nv < NDET) ? nv : NDET;

    // load precomputed histogram, re-zero global copy
    for (int i = tid; i < HBINS; i += 256) {
        sm.tk.hist[i] = g_hist[b * HBINS + i];
        g_hist[b * HBINS + i] = 0;
    }
    if (tid == 0) { gcnt_s = 0; pb_s = 0; }
    __syncthreads();

    // hierarchical inclusive suffix sum: 256 threads x 8 contiguous bins
    {
        int loc[8];
        int s = 0;
        #pragma unroll
        for (int k = 7; k >= 0; k--) { s += sm.tk.hist[tid * 8 + k]; loc[k] = s; }
        int tot = s;
        int suf = tot;
        #pragma unroll
        for (int o = 1; o < 32; o <<= 1) {
            int v = __shfl_down_sync(FULLM, suf, o);
            if (lane + o < 32) suf += v;          // suf = sum of lanes >= lane
        }
        if (lane == 0) sm.tk.warpsum[wid] = suf;
        __syncthreads();
        if (wid == 0) {
            int cs = (lane < 8) ? sm.tk.warpsum[lane] : 0;
            int a2 = cs;
            #pragma unroll
            for (int o = 1; o < 8; o <<= 1) {
                int v = __shfl_down_sync(FULLM, a2, o);
                if (lane + o < 8) a2 += v;
            }
            if (lane < 8) sm.tk.warp_above[lane] = a2 - cs;
        }
        __syncthreads();
        int above = sm.tk.warp_above[wid] + (suf - tot);
        #pragma unroll
        for (int k = 0; k < 8; k++) sm.tk.hist[tid * 8 + k] = loc[k] + above;
    }
    __syncthreads();

    // pivot bucket: largest i with suffix >= nsel
    if (nsel > 0) {
        for (int i = tid; i < HBINS; i += 256) {
            int s = sm.tk.hist[i];
            int sn = (i + 1 < HBINS) ? sm.tk.hist[i + 1] : 0;
            if (s >= nsel && sn < nsel) pb_s = i;
        }
    }
    __syncthreads();
    const int pb = pb_s;
    const int m  = (nsel > 0) ? sm.tk.hist[pb] : 0;

    if (m <= GCAP2) {
        for (int j = tid; j < nv; j += 256) {
            unsigned k = __float_as_uint(g_svsc[sbase + j]);
            if (score_bkt(k) >= pb) {
                int slot = atomicAdd(&gcnt_s, 1);
                sm.tk.keys[slot] = ((unsigned long long)k << 32) | (unsigned)(~j);
            }
        }
        __syncthreads();
        for (int i = tid; i < m; i += 256) {
            unsigned long long ki = sm.tk.keys[i];
            int r = 0;
            for (int j = 0; j < m; j++) r += (sm.tk.keys[j] > ki);
            sm.tk.skeys[r] = ki;
        }
        __syncthreads();
    } else {
        // destructive argmax fallback (pathological tie pile-up only)
        for (int it = 0; it < nsel; it++) {
            float bv = -2e9f; int bi = 0;
            for (int j = tid; j < nv; j += 256) {
                float v = g_svsc[sbase + j];
                if (v > bv) { bv = v; bi = j; }
            }
            #pragma unroll
            for (int o = 16; o; o >>= 1) {
                float ov = __shfl_xor_sync(FULLM, bv, o);
                int   oi = __shfl_xor_sync(FULLM, bi, o);
                if (ov > bv || (ov == bv && oi < bi)) { bv = ov; bi = oi; }
            }
            if ((tid & 31) == 0) { red_v[tid >> 5] = bv; red_i[tid >> 5] = bi; }
            __syncthreads();
            if (tid == 0) {
                for (int wv = 1; wv < 8; wv++)
                    if (red_v[wv] > red_v[0] ||
                        (red_v[wv] == red_v[0] && red_i[wv] < red_i[0])) {
                        red_v[0] = red_v[wv]; red_i[0] = red_i[wv];
                    }
                int bsel = red_i[0];
                sm.tk.skeys[it] =
                    ((unsigned long long)__float_as_uint(red_v[0]) << 32)
                  | (unsigned)(~bsel);
                g_svsc[sbase + bsel] = NEGV;
            }
            __syncthreads();
        }
    }

    // emit: [boxes 8*100*4][scores 8*100][labels 8*100][keep 8*100]
    const int SC0 = B_IMG * NDET * 4;
    const int LB0 = SC0 + B_IMG * NDET;
    const int KP0 = LB0 + B_IMG * NDET;
    for (int i = tid; i < NDET; i += 256) {
        float4 bx = make_float4(0.f, 0.f, 0.f, 0.f);
        float sc = 0.0f, lb = 0.0f, kp = 0.0f;
        if (i < nsel) {
            unsigned long long kk = sm.tk.skeys[i];
            int j = (int)(~(unsigned)kk);
            bx = g_svbox[sbase + j];
            sc = __uint_as_float((unsigned)(kk >> 32));
            lb = (float)g_svlab[sbase + j];
            kp = 1.0f;
        }
        float* ob = out + ((size_t)b * NDET + i) * 4;
        ob[0] = bx.x; ob[1] = bx.y; ob[2] = bx.z; ob[3] = bx.w;
        out[SC0 + b * NDET + i] = sc;
        out[LB0 + b * NDET + i] = lb;
        out[KP0 + b * NDET + i] = kp;
    }
    __syncthreads();
    if (tid == 0) {
        g_svcnt[b] = 0;   // self-reset for next graph replay
        g_done[b]  = 0;
    }
}

extern "C" void kernel_launch(void* const* d_in, const int* in_sizes, int n_in,
                              void* d_out, int out_size) {
    const float* logits = (const float*)d_in[0];
    const float* reg    = (const float*)d_in[1];
    const float* props  = (const float*)d_in[2];
    const int*   ih     = (const int*)d_in[3];
    const int*   iw     = (const int*)d_in[4];
    float* out = (float*)d_out;

    phaseAB_kernel<<<NBLKA, 256>>>(logits, reg, props, ih, iw);
    nms_topk_kernel<<<dim3(NCM1, B_IMG), 256>>>(out, ih, iw);
}

// round 12
// speedup vs baseline: 1.0557x; 1.0328x over previous
#include <cuda_runtime.h>
#include <cstdint>
#include <math.h>

#define B_IMG 8
#define NPROP 4000
#define NCLS 91
#define NCM1 90
#define CAPC 4000                    // worst-case candidates per (image,class)
#define NDET 100
#define NEGV -1e9f
#define CAPSM 512                    // smem sort cap for class NMS
#define MASKN 320                    // mask-path cap
#define MW 10                        // u32 mask words per row (MASKN/32)
#define SV_PER_IMG (NCM1 * NDET)     // 9000 survivors per image (capped)
#define GCAP2 512                    // topk gather capacity
#define HBINS 2048
#define HLO 30720                    // (key>>15) offset; covers scores >~0.0078
#define NBLKA 2000                   // phaseAB blocks (16 proposals each)
#define QCAP 320                     // smem queue cap (<=20 passers/proposal)
#define FULLM 0xffffffffu

static __device__ float4        g_cbox[B_IMG * NCM1 * CAPC];
static __device__ float         g_cs[B_IMG * NCM1 * CAPC];
static __device__ int           g_ccnt[B_IMG * NCM1];    // zero-init, self-reset
static __device__ float4        g_svbox[B_IMG * SV_PER_IMG];
static __device__ float         g_svsc[B_IMG * SV_PER_IMG];
static __device__ unsigned char g_svlab[B_IMG * SV_PER_IMG];
static __device__ int           g_svcnt[B_IMG];          // zero-init, self-reset
static __device__ int           g_hist[B_IMG * HBINS];   // zero-init, self-reset
static __device__ int           g_done[B_IMG];           // zero-init, self-reset

__device__ __forceinline__ float load_dim(const int* p) {
    int vi = *p;
    if (vi > 0 && vi < 1000000) return (float)vi;
    return __int_as_float(vi);
}

__device__ __forceinline__ int score_bkt(unsigned keybits) {
    int bkt = (int)(keybits >> 15) - HLO;
    return max(0, min(HBINS - 1, bkt));
}

// ---------------------------------------------------------------------------
// Phase AB (fused): softmax + threshold filter -> smem queue -> dense decode.
// (unchanged — measured 19.3us)
// ---------------------------------------------------------------------------
__global__ void __launch_bounds__(256)
phaseAB_kernel(const float* __restrict__ logits,
               const float* __restrict__ reg,
               const float* __restrict__ props,
               const int* __restrict__ ph,
               const int* __restrict__ pw) {
    const int warp = threadIdx.x >> 5;
    const int lane = threadIdx.x & 31;
    const int p0 = (blockIdx.x * 8 + warp) << 1;

    __shared__ unsigned long long q[QCAP];
    __shared__ int s_cnt;
    if (threadIdx.x == 0) s_cnt = 0;
    __syncthreads();

    const float* z0 = logits + (size_t)p0 * NCLS;
    const float* z1 = z0 + NCLS;

    float e[2][3];
    e[0][0] = __expf(z0[lane]);
    e[1][0] = __expf(z1[lane]);
    e[0][1] = __expf(z0[lane + 32]);
    e[1][1] = __expf(z1[lane + 32]);
    e[0][2] = (lane < NCLS - 64) ? __expf(z0[lane + 64]) : 0.0f;
    e[1][2] = (lane < NCLS - 64) ? __expf(z1[lane + 64]) : 0.0f;

    float ssum[2];
    ssum[0] = e[0][0] + e[0][1] + e[0][2];
    ssum[1] = e[1][0] + e[1][1] + e[1][2];
    #pragma unroll
    for (int o = 16; o; o >>= 1) {
        ssum[0] += __shfl_xor_sync(FULLM, ssum[0], o);
        ssum[1] += __shfl_xor_sync(FULLM, ssum[1], o);
    }

    bool pass[6];
    int cnt = 0;
    #pragma unroll
    for (int k = 0; k < 2; k++) {
        float thr = 0.05f * ssum[k];
        #pragma unroll
        for (int t = 0; t < 3; t++) {
            int c = lane + 32 * t;
            bool pk = (c > 0) && (c < NCLS) && (e[k][t] > thr);
            pass[k * 3 + t] = pk;
            cnt += pk ? 1 : 0;
        }
    }

    int incl = cnt;
    #pragma unroll
    for (int o = 1; o < 32; o <<= 1) {
        int v = __shfl_up_sync(FULLM, incl, o);
        if (lane >= o) incl += v;
    }
    int total = __shfl_sync(FULLM, incl, 31);
    int wbase = 0;
    if (total > 0) {
        if (lane == 31) wbase = atomicAdd(&s_cnt, total);
        wbase = __shfl_sync(FULLM, wbase, 31);
        int off = wbase + incl - cnt;
        #pragma unroll
        for (int k = 0; k < 2; k++) {
            #pragma unroll
            for (int t = 0; t < 3; t++) {
                if (pass[k * 3 + t]) {
                    int c = lane + 32 * t;
                    float sc = e[k][t] / ssum[k];
                    unsigned idx = ((unsigned)(p0 + k) << 7) | (unsigned)c;
                    q[off++] = ((unsigned long long)__float_as_uint(sc) << 32) | idx;
                }
            }
        }
    }
    __syncthreads();

    const int qcnt = s_cnt;
    const float Wf = load_dim(pw);
    const float Hf = load_dim(ph);
    const float CLIPV = 4.135166556742356f;  // log(1000/16)

    for (int i = threadIdx.x; i < qcnt; i += 256) {
        unsigned long long en = q[i];
        float sc = __uint_as_float((unsigned)(en >> 32));
        unsigned idx = (unsigned)en;
        int p = idx >> 7, c = idx & 127;

        float4 pr = ((const float4*)props)[p];
        float w = pr.z - pr.x, h = pr.w - pr.y;
        float cx = pr.x + 0.5f * w, cy = pr.y + 0.5f * h;
        float4 r = ((const float4*)reg)[p * NCLS + c];

        float dx = r.x / 10.0f, dy = r.y / 10.0f;
        float dw = fminf(r.z / 5.0f, CLIPV);
        float dh = fminf(r.w / 5.0f, CLIPV);
        float pcx = dx * w + cx, pcy = dy * h + cy;
        float pwd = __expf(dw) * w, phd = __expf(dh) * h;
        float x1 = pcx - 0.5f * pwd, y1 = pcy - 0.5f * phd;
        float x2 = pcx + 0.5f * pwd, y2 = pcy + 0.5f * phd;
        x1 = fminf(fmaxf(x1, 0.0f), Wf); x2 = fminf(fmaxf(x2, 0.0f), Wf);
        y1 = fminf(fmaxf(y1, 0.0f), Hf); y2 = fminf(fmaxf(y2, 0.0f), Hf);
        if ((x2 - x1) >= 0.01f && (y2 - y1) >= 0.01f) {
            int b = p / NPROP;
            int bc = b * NCM1 + (c - 1);
            int pos = atomicAdd(&g_ccnt[bc], 1);
            size_t o = (size_t)bc * CAPC + pos;
            g_cbox[o] = make_float4(x1, y1, x2, y2);
            g_cs[o]   = sc;
        }
    }
}

// ---------------------------------------------------------------------------
// Fused NMS + topk. NMS core rewritten for issue-throughput:
//  - ballot-popc rank sort (warp per i, coalesced LDS)
//  - warp-per-row u32 suppression mask via __ballot_sync
//  - greedy scan on warp 0 with dead-words in registers (lane L owns word L)
// Last-finished block per image runs radix-select top-100 inline.
// ---------------------------------------------------------------------------
struct NmsSm {
    unsigned long long skey[CAPSM];          // 4KB
    unsigned long long ssort[CAPSM];         // 4KB
    float4             sbox[CAPSM];          // 8KB
    float              sarea[CAPSM];         // 2KB
    unsigned int       mrow[MASKN * MW];     // 12.5KB
    unsigned char      alive[CAPSM];         // 0.5KB
};
struct TopkSm {
    int                hist[HBINS];          // 8KB
    unsigned long long keys[GCAP2];          // 4KB
    unsigned long long skeys[GCAP2];         // 4KB
    int                warpsum[8];
    int                warp_above[8];
};
union SmU { NmsSm nms; TopkSm tk; };

__global__ void __launch_bounds__(256)
nms_topk_kernel(float* __restrict__ out,
                const int* __restrict__ ph, const int* __restrict__ pw) {
    const int c  = blockIdx.x + 1;
    const int b  = blockIdx.y;
    const int bc = b * NCM1 + (c - 1);
    const int tid = threadIdx.x;
    const int wid = tid >> 5;
    const int lane = tid & 31;
    const int n = g_ccnt[bc];

    __shared__ SmU sm;
    __shared__ unsigned short surv[NDET];
    __shared__ int            nsurv_s, sbase_s, lastf;
    __shared__ float          red_v[8];
    __shared__ int            red_i[8];
    __shared__ int            stop_s, seli_s, gcnt_s, pb_s;
    __shared__ float4         selbox_s;
    __shared__ float          gsc_s;

    const size_t base = (size_t)bc * CAPC;

    // =================== NMS phase ===================
    if (n > 0 && n <= CAPSM) {
        const int NW32 = (n + 31) >> 5;

        for (int j = tid; j < n; j += 256)
            sm.nms.skey[j] =
                ((unsigned long long)__float_as_uint(g_cs[base + j]) << 32)
              | (unsigned)j;
        __syncthreads();

        // ballot-popc rank sort: warp per i, lanes scan j in 32-chunks
        for (int i = wid; i < n; i += 8) {
            unsigned long long ki = sm.nms.skey[i];
            int r = 0;
            for (int jb = 0; jb < NW32; jb++) {
                int j = (jb << 5) + lane;
                bool g = (j < n) && (sm.nms.skey[j] > ki);
                r += __popc(__ballot_sync(FULLM, g));
            }
            if (lane == 0) sm.nms.ssort[r] = ki;
        }
        __syncthreads();

        // gather boxes + areas into sorted order
        for (int i = tid; i < n; i += 256) {
            float4 bx = g_cbox[base + (unsigned)(sm.nms.ssort[i] & 0xffffffffu)];
            sm.nms.sbox[i]  = bx;
            sm.nms.sarea[i] = (bx.z - bx.x) * (bx.w - bx.y);
        }
        __syncthreads();

        if (n <= MASKN) {
            // ---- u32 ballot mask build: warp per row i ----
            for (int i = wid; i < n; i += 8) {
                float4 bi = sm.nms.sbox[i];
                float ai  = sm.nms.sarea[i];
                for (int jb = i >> 5; jb < NW32; jb++) {
                    int j = (jb << 5) + lane;
                    bool sup = false;
                    if (j > i && j < n) {
                        float4 bj = sm.nms.sbox[j];
                        float ix1 = fmaxf(bi.x, bj.x), iy1 = fmaxf(bi.y, bj.y);
                        float ix2 = fminf(bi.z, bj.z), iy2 = fminf(bi.w, bj.w);
                        float inter = fmaxf(ix2 - ix1, 0.0f) * fmaxf(iy2 - iy1, 0.0f);
                        sup = inter > 0.5f * (ai + sm.nms.sarea[j] - inter);
                    }
                    unsigned bits = __ballot_sync(FULLM, sup);
                    if (lane == 0) sm.nms.mrow[i * MW + jb] = bits;
                }
            }
            __syncthreads();

            // ---- greedy scan, warp 0, dead-words in registers ----
            if (wid == 0) {
                unsigned dead = 0;    // lane L holds dead word L (j in [32L,32L+32))
                int ns = 0;
                for (int i = 0; i < n && ns < NDET; i++) {
                    unsigned dw = __shfl_sync(FULLM, dead, i >> 5);
                    if (!((dw >> (i & 31)) & 1u)) {
                        if (lane == 0) surv[ns] = (unsigned short)i;
                        ns++;
                        if (lane < NW32 && lane >= (i >> 5))
                            dead |= sm.nms.mrow[i * MW + lane];
                    }
                }
                if (lane == 0) {
                    nsurv_s = ns;
                    sbase_s = atomicAdd(&g_svcnt[b], ns);
                }
            }
        } else {
            // ---- maskless warp-greedy mid path (320 < n <= 512) ----
            for (int i = tid; i < n; i += 256) sm.nms.alive[i] = 1;
            __syncthreads();
            if (wid == 0) {
                int ns = 0;
                for (int i = 0; i < n && ns < NDET; i++) {
                    if (sm.nms.alive[i] == 0) continue;
                    if (lane == 0) surv[ns] = (unsigned short)i;
                    ns++;
                    float4 bi = sm.nms.sbox[i];
                    float ai = sm.nms.sarea[i];
                    for (int j = i + 1 + lane; j < n; j += 32) {
                        if (!sm.nms.alive[j]) continue;
                        float4 bj = sm.nms.sbox[j];
                        float ix1 = fmaxf(bi.x, bj.x), iy1 = fmaxf(bi.y, bj.y);
                        float ix2 = fminf(bi.z, bj.z), iy2 = fminf(bi.w, bj.w);
                        float inter = fmaxf(ix2 - ix1, 0.0f) * fmaxf(iy2 - iy1, 0.0f);
                        if (inter > 0.5f * (ai + sm.nms.sarea[j] - inter))
                            sm.nms.alive[j] = 0;
                    }
                    __syncwarp();
                }
                if (lane == 0) {
                    nsurv_s = ns;
                    sbase_s = atomicAdd(&g_svcnt[b], ns);
                }
            }
        }
        __syncthreads();

        const int so = b * SV_PER_IMG + sbase_s;
        for (int s = tid; s < nsurv_s; s += 256) {
            int i = surv[s];
            unsigned kb = (unsigned)(sm.nms.ssort[i] >> 32);
            g_svbox[so + s] = sm.nms.sbox[i];
            g_svsc[so + s]  = __uint_as_float(kb);
            g_svlab[so + s] = (unsigned char)c;
            atomicAdd(&g_hist[b * HBINS + score_bkt(kb)], 1);
        }
    } else if (n > CAPSM) {
        // ---- global argmax fallback (essentially never) ----
        const float Hf = load_dim(ph);
        const float Wf = load_dim(pw);
        const float off = fmaxf(Hf, Wf) + 1.0f;
        const float t = (float)c * off;
        for (int it = 0; it < NDET; it++) {
            float bv = -2e9f; int bi = 0;
            for (int j = tid; j < n; j += 256) {
                float v = g_cs[base + j];
                if (v > bv) { bv = v; bi = j; }
            }
            #pragma unroll
            for (int o = 16; o; o >>= 1) {
                float ov = __shfl_xor_sync(FULLM, bv, o);
                int   oi = __shfl_xor_sync(FULLM, bi, o);
                if (ov > bv || (ov == bv && oi < bi)) { bv = ov; bi = oi; }
            }
            if (lane == 0) { red_v[wid] = bv; red_i[wid] = bi; }
            __syncthreads();
            if (tid == 0) {
                for (int wv = 1; wv < 8; wv++)
                    if (red_v[wv] > red_v[0] ||
                        (red_v[wv] == red_v[0] && red_i[wv] < red_i[0])) {
                        red_v[0] = red_v[wv]; red_i[0] = red_i[wv];
                    }
                if (red_v[0] < -5e8f) stop_s = 1;
                else {
                    stop_s = 0; seli_s = red_i[0];
                    selbox_s = g_cbox[base + red_i[0]];
                    gsc_s = red_v[0];
                }
            }
            __syncthreads();
            if (stop_s) break;
            float4 bx = selbox_s;
            float ox1 = bx.x + t, oy1 = bx.y + t, ox2 = bx.z + t, oy2 = bx.w + t;
            float ai = (ox2 - ox1) * (oy2 - oy1);
            for (int j = tid; j < n; j += 256) {
                float v = g_cs[base + j];
                if (v < -5e8f) continue;
                float4 bj = g_cbox[base + j];
                float jx1 = bj.x + t, jy1 = bj.y + t, jx2 = bj.z + t, jy2 = bj.w + t;
                float ix1 = fmaxf(ox1, jx1), iy1 = fmaxf(oy1, jy1);
                float ix2 = fminf(ox2, jx2), iy2 = fminf(oy2, jy2);
                float inter = fmaxf(ix2 - ix1, 0.0f) * fmaxf(iy2 - iy1, 0.0f);
                float aj = (jx2 - jx1) * (jy2 - jy1);
                if (inter > 0.5f * (ai + aj - inter)) g_cs[base + j] = NEGV;
            }
            __syncthreads();
            if (tid == 0) {
                g_cs[base + seli_s] = NEGV;
                int slot = atomicAdd(&g_svcnt[b], 1);
                g_svbox[b * SV_PER_IMG + slot] = selbox_s;
                g_svsc[b * SV_PER_IMG + slot]  = gsc_s;
                g_svlab[b * SV_PER_IMG + slot] = (unsigned char)c;
                atomicAdd(&g_hist[b * HBINS + score_bkt(__float_as_uint(gsc_s))], 1);
            }
            __syncthreads();
        }
    }

    // ============ release-arrive on per-image done counter ============
    __threadfence();
    __syncthreads();
    if (tid == 0) {
        if (n > 0) g_ccnt[bc] = 0;                 // self-reset for replay
        lastf = (atomicAdd(&g_done[b], 1) == NCM1 - 1);
    }
    __syncthreads();
    if (!lastf) return;
    __threadfence();                               // acquire all blocks' writes

    // =================== topk phase (last block only) ===================
    const int nv = g_svcnt[b];
    const int sbase = b * SV_PER_IMG;
    const int nsel = (nv < NDET) ? nv : NDET;

    for (int i = tid; i < HBINS; i += 256) {
        sm.tk.hist[i] = g_hist[b * HBINS + i];
        g_hist[b * HBINS + i] = 0;
    }
    if (tid == 0) { gcnt_s = 0; pb_s = 0; }
    __syncthreads();

    // hierarchical inclusive suffix sum: 256 threads x 8 contiguous bins
    {
        int loc[8];
        int s = 0;
        #pragma unroll
        for (int k = 7; k >= 0; k--) { s += sm.tk.hist[tid * 8 + k]; loc[k] = s; }
        int tot = s;
        int suf = tot;
        #pragma unroll
        for (int o = 1; o < 32; o <<= 1) {
            int v = __shfl_down_sync(FULLM, suf, o);
            if (lane + o < 32) suf += v;
        }
        if (lane == 0) sm.tk.warpsum[wid] = suf;
        __syncthreads();
        if (wid == 0) {
            int cs = (lane < 8) ? sm.tk.warpsum[lane] : 0;
            int a2 = cs;
            #pragma unroll
            for (int o = 1; o < 8; o <<= 1) {
                int v = __shfl_down_sync(FULLM, a2, o);
                if (lane + o < 8) a2 += v;
            }
            if (lane < 8) sm.tk.warp_above[lane] = a2 - cs;
        }
        __syncthreads();
        int above = sm.tk.warp_above[wid] + (suf - tot);
        #pragma unroll
        for (int k = 0; k < 8; k++) sm.tk.hist[tid * 8 + k] = loc[k] + above;
    }
    __syncthreads();

    if (nsel > 0) {
        for (int i = tid; i < HBINS; i += 256) {
            int s = sm.tk.hist[i];
            int sn = (i + 1 < HBINS) ? sm.tk.hist[i + 1] : 0;
            if (s >= nsel && sn < nsel) pb_s = i;
        }
    }
    __syncthreads();
    const int pb = pb_s;
    const int m  = (nsel > 0) ? sm.tk.hist[pb] : 0;

    if (m <= GCAP2) {
        for (int j = tid; j < nv; j += 256) {
            unsigned k = __float_as_uint(g_svsc[sbase + j]);
            if (score_bkt(k) >= pb) {
                int slot = atomicAdd(&gcnt_s, 1);
                sm.tk.keys[slot] = ((unsigned long long)k << 32) | (unsigned)(~j);
            }
        }
        __syncthreads();
        for (int i = tid; i < m; i += 256) {
            unsigned long long ki = sm.tk.keys[i];
            int r = 0;
            for (int j = 0; j < m; j++) r += (sm.tk.keys[j] > ki);
            sm.tk.skeys[r] = ki;
        }
        __syncthreads();
    } else {
        for (int it = 0; it < nsel; it++) {
            float bv = -2e9f; int bi = 0;
            for (int j = tid; j < nv; j += 256) {
                float v = g_svsc[sbase + j];
                if (v > bv) { bv = v; bi = j; }
            }
            #pragma unroll
            for (int o = 16; o; o >>= 1) {
                float ov = __shfl_xor_sync(FULLM, bv, o);
                int   oi = __shfl_xor_sync(FULLM, bi, o);
                if (ov > bv || (ov == bv && oi < bi)) { bv = ov; bi = oi; }
            }
            if (lane == 0) { red_v[wid] = bv; red_i[wid] = bi; }
            __syncthreads();
            if (tid == 0) {
                for (int wv = 1; wv < 8; wv++)
                    if (red_v[wv] > red_v[0] ||
                        (red_v[wv] == red_v[0] && red_i[wv] < red_i[0])) {
                        red_v[0] = red_v[wv]; red_i[0] = red_i[wv];
                    }
                int bsel = red_i[0];
                sm.tk.skeys[it] =
                    ((unsigned long long)__float_as_uint(red_v[0]) << 32)
                  | (unsigned)(~bsel);
                g_svsc[sbase + bsel] = NEGV;
            }
            __syncthreads();
        }
    }

    // emit: [boxes 8*100*4][scores 8*100][labels 8*100][keep 8*100]
    const int SC0 = B_IMG * NDET * 4;
    const int LB0 = SC0 + B_IMG * NDET;
    const int KP0 = LB0 + B_IMG * NDET;
    for (int i = tid; i < NDET; i += 256) {
        float4 bx = make_float4(0.f, 0.f, 0.f, 0.f);
        float sc = 0.0f, lb = 0.0f, kp = 0.0f;
        if (i < nsel) {
            unsigned long long kk = sm.tk.skeys[i];
            int j = (int)(~(unsigned)kk);
            bx = g_svbox[sbase + j];
            sc = __uint_as_float((unsigned)(kk >> 32));
            lb = (float)g_svlab[sbase + j];
            kp = 1.0f;
        }
        float* ob = out + ((size_t)b * NDET + i) * 4;
        ob[0] = bx.x; ob[1] = bx.y; ob[2] = bx.z; ob[3] = bx.w;
        out[SC0 + b * NDET + i] = sc;
        out[LB0 + b * NDET + i] = lb;
        out[KP0 + b * NDET + i] = kp;
    }
    __syncthreads();
    if (tid == 0) {
        g_svcnt[b] = 0;   // self-reset for next graph replay
        g_done[b]  = 0;
    }
}

extern "C" void kernel_launch(void* const* d_in, const int* in_sizes, int n_in,
                              void* d_out, int out_size) {
    const float* logits = (const float*)d_in[0];
    const float* reg    = (const float*)d_in[1];
    const float* props  = (const float*)d_in[2];
    const int*   ih     = (const int*)d_in[3];
    const int*   iw     = (const int*)d_in[4];
    float* out = (float*)d_out;

    phaseAB_kernel<<<NBLKA, 256>>>(logits, reg, props, ih, iw);
    nms_topk_kernel<<<dim3(NCM1, B_IMG), 256>>>(out, ih, iw);
}

// round 14
// speedup vs baseline: 1.2396x; 1.1743x over previous
#include <cuda_runtime.h>
#include <cstdint>
#include <math.h>

#define B_IMG 8
#define NPROP 4000
#define NCLS 91
#define NCM1 90
#define CAPC 4000                    // worst-case candidates per (image,class)
#define NDET 100
#define NEGV -1e9f
#define CAPSM 512                    // smem sort cap for class NMS
#define MASKN 320                    // mask-path cap
#define MW 10                        // u32 mask words per row (MASKN/32)
#define SV_PER_IMG (NCM1 * NDET)     // 9000 survivors per image (capped)
#define GCAP 1024                    // topk gather capacity
#define HBINS 2048
#define HLO 30720                    // (key>>15) offset; covers scores >~0.0078
#define NBLKA 2000                   // phaseAB blocks (16 proposals each)
#define QCAP 320                     // smem queue cap (<=20 passers/proposal)
#define FULLM 0xffffffffu

static __device__ float4        g_cbox[B_IMG * NCM1 * CAPC];
static __device__ float         g_cs[B_IMG * NCM1 * CAPC];
static __device__ int           g_ccnt[B_IMG * NCM1];    // zero-init, self-reset
static __device__ float4        g_svbox[B_IMG * SV_PER_IMG];
static __device__ float         g_svsc[B_IMG * SV_PER_IMG];
static __device__ unsigned char g_svlab[B_IMG * SV_PER_IMG];
static __device__ int           g_svcnt[B_IMG];          // zero-init, self-reset
static __device__ int           g_hist[B_IMG * HBINS];   // zero-init, topk re-zeros

__device__ __forceinline__ float load_dim(const int* p) {
    int vi = *p;
    if (vi > 0 && vi < 1000000) return (float)vi;
    return __int_as_float(vi);
}

__device__ __forceinline__ int score_bkt(unsigned keybits) {
    int bkt = (int)(keybits >> 15) - HLO;
    return max(0, min(HBINS - 1, bkt));
}

// ---------------------------------------------------------------------------
// Phase AB (fused): softmax + threshold filter -> smem queue -> dense decode.
// (unchanged — measured 19.3us)
// ---------------------------------------------------------------------------
__global__ void __launch_bounds__(256)
phaseAB_kernel(const float* __restrict__ logits,
               const float* __restrict__ reg,
               const float* __restrict__ props,
               const int* __restrict__ ph,
               const int* __restrict__ pw) {
    const int warp = threadIdx.x >> 5;
    const int lane = threadIdx.x & 31;
    const int p0 = (blockIdx.x * 8 + warp) << 1;

    __shared__ unsigned long long q[QCAP];
    __shared__ int s_cnt;
    if (threadIdx.x == 0) s_cnt = 0;
    __syncthreads();

    const float* z0 = logits + (size_t)p0 * NCLS;
    const float* z1 = z0 + NCLS;

    float e[2][3];
    e[0][0] = __expf(z0[lane]);
    e[1][0] = __expf(z1[lane]);
    e[0][1] = __expf(z0[lane + 32]);
    e[1][1] = __expf(z1[lane + 32]);
    e[0][2] = (lane < NCLS - 64) ? __expf(z0[lane + 64]) : 0.0f;
    e[1][2] = (lane < NCLS - 64) ? __expf(z1[lane + 64]) : 0.0f;

    float ssum[2];
    ssum[0] = e[0][0] + e[0][1] + e[0][2];
    ssum[1] = e[1][0] + e[1][1] + e[1][2];
    #pragma unroll
    for (int o = 16; o; o >>= 1) {
        ssum[0] += __shfl_xor_sync(FULLM, ssum[0], o);
        ssum[1] += __shfl_xor_sync(FULLM, ssum[1], o);
    }

    bool pass[6];
    int cnt = 0;
    #pragma unroll
    for (int k = 0; k < 2; k++) {
        float thr = 0.05f * ssum[k];
        #pragma unroll
        for (int t = 0; t < 3; t++) {
            int c = lane + 32 * t;
            bool pk = (c > 0) && (c < NCLS) && (e[k][t] > thr);
            pass[k * 3 + t] = pk;
            cnt += pk ? 1 : 0;
        }
    }

    int incl = cnt;
    #pragma unroll
    for (int o = 1; o < 32; o <<= 1) {
        int v = __shfl_up_sync(FULLM, incl, o);
        if (lane >= o) incl += v;
    }
    int total = __shfl_sync(FULLM, incl, 31);
    int wbase = 0;
    if (total > 0) {
        if (lane == 31) wbase = atomicAdd(&s_cnt, total);
        wbase = __shfl_sync(FULLM, wbase, 31);
        int off = wbase + incl - cnt;
        #pragma unroll
        for (int k = 0; k < 2; k++) {
            #pragma unroll
            for (int t = 0; t < 3; t++) {
                if (pass[k * 3 + t]) {
                    int c = lane + 32 * t;
                    float sc = e[k][t] / ssum[k];
                    unsigned idx = ((unsigned)(p0 + k) << 7) | (unsigned)c;
                    q[off++] = ((unsigned long long)__float_as_uint(sc) << 32) | idx;
                }
            }
        }
    }
    __syncthreads();

    const int qcnt = s_cnt;
    const float Wf = load_dim(pw);
    const float Hf = load_dim(ph);
    const float CLIPV = 4.135166556742356f;  // log(1000/16)

    for (int i = threadIdx.x; i < qcnt; i += 256) {
        unsigned long long en = q[i];
        float sc = __uint_as_float((unsigned)(en >> 32));
        unsigned idx = (unsigned)en;
        int p = idx >> 7, c = idx & 127;

        float4 pr = ((const float4*)props)[p];
        float w = pr.z - pr.x, h = pr.w - pr.y;
        float cx = pr.x + 0.5f * w, cy = pr.y + 0.5f * h;
        float4 r = ((const float4*)reg)[p * NCLS + c];

        float dx = r.x / 10.0f, dy = r.y / 10.0f;
        float dw = fminf(r.z / 5.0f, CLIPV);
        float dh = fminf(r.w / 5.0f, CLIPV);
        float pcx = dx * w + cx, pcy = dy * h + cy;
        float pwd = __expf(dw) * w, phd = __expf(dh) * h;
        float x1 = pcx - 0.5f * pwd, y1 = pcy - 0.5f * phd;
        float x2 = pcx + 0.5f * pwd, y2 = pcy + 0.5f * phd;
        x1 = fminf(fmaxf(x1, 0.0f), Wf); x2 = fminf(fmaxf(x2, 0.0f), Wf);
        y1 = fminf(fmaxf(y1, 0.0f), Hf); y2 = fminf(fmaxf(y2, 0.0f), Hf);
        if ((x2 - x1) >= 0.01f && (y2 - y1) >= 0.01f) {
            int b = p / NPROP;
            int bc = b * NCM1 + (c - 1);
            int pos = atomicAdd(&g_ccnt[bc], 1);
            size_t o = (size_t)bc * CAPC + pos;
            g_cbox[o] = make_float4(x1, y1, x2, y2);
            g_cs[o]   = sc;
        }
    }
}

// ---------------------------------------------------------------------------
// Phase B: one block per (image,class). x4-row ballot rank sort + x4-row
// ballot mask build (amortizes LDS/predicate/loop overhead over 4 rows),
// warp-0 register greedy scan. Survivors + per-image histogram to global.
// ---------------------------------------------------------------------------
__global__ void __launch_bounds__(256, 5)
class_nms_kernel(const int* __restrict__ ph, const int* __restrict__ pw) {
    const int c  = blockIdx.x + 1;
    const int b  = blockIdx.y;
    const int bc = b * NCM1 + (c - 1);
    const int tid = threadIdx.x;
    const int wid = tid >> 5;
    const int lane = tid & 31;
    const int n = g_ccnt[bc];
    if (n == 0) return;

    __shared__ unsigned long long skey[CAPSM];
    __shared__ unsigned long long ssort[CAPSM];
    __shared__ float4             sbox[CAPSM];
    __shared__ float              sarea[CAPSM];
    __shared__ unsigned int       mrow[MASKN * MW];
    __shared__ unsigned char      alive[CAPSM];
    __shared__ unsigned short     surv[NDET];
    __shared__ int                nsurv_s, sbase_s;
    __shared__ float              red_v[8];
    __shared__ int                red_i[8];
    __shared__ int                stop_s, seli_s;
    __shared__ float4             selbox_s;
    __shared__ float              gsc_s;

    const size_t base = (size_t)bc * CAPC;

    if (n <= CAPSM) {
        const int NW32 = (n + 31) >> 5;
        const int im = n - 1;

        for (int j = tid; j < n; j += 256)
            skey[j] = ((unsigned long long)__float_as_uint(g_cs[base + j]) << 32)
                    | (unsigned)j;
        __syncthreads();

        // x4-row ballot rank sort
        for (int i0 = wid << 2; i0 < n; i0 += 32) {
            unsigned long long k0 = skey[i0];
            unsigned long long k1 = skey[min(i0 + 1, im)];
            unsigned long long k2 = skey[min(i0 + 2, im)];
            unsigned long long k3 = skey[min(i0 + 3, im)];
            int r0 = 0, r1 = 0, r2 = 0, r3 = 0;
            for (int jb = 0; jb < NW32; jb++) {
                int j = (jb << 5) + lane;
                bool v = j < n;
                unsigned long long kj = skey[v ? j : 0];
                r0 += __popc(__ballot_sync(FULLM, v && (kj > k0)));
                r1 += __popc(__ballot_sync(FULLM, v && (kj > k1)));
                r2 += __popc(__ballot_sync(FULLM, v && (kj > k2)));
                r3 += __popc(__ballot_sync(FULLM, v && (kj > k3)));
            }
            if (lane < 4 && i0 + lane < n) {
                int rr = (lane == 0) ? r0 : (lane == 1) ? r1 : (lane == 2) ? r2 : r3;
                unsigned long long kk =
                    (lane == 0) ? k0 : (lane == 1) ? k1 : (lane == 2) ? k2 : k3;
                ssort[rr] = kk;
            }
        }
        __syncthreads();

        for (int i = tid; i < n; i += 256) {
            float4 bx = g_cbox[base + (unsigned)(ssort[i] & 0xffffffffu)];
            sbox[i]  = bx;
            sarea[i] = (bx.z - bx.x) * (bx.w - bx.y);
        }
        __syncthreads();

        if (n <= MASKN) {
            // ---- x4-row ballot mask build ----
            for (int i0 = wid << 2; i0 < n; i0 += 32) {
                float4 b0 = sbox[i0];
                float4 b1 = sbox[min(i0 + 1, im)];
                float4 b2 = sbox[min(i0 + 2, im)];
                float4 b3 = sbox[min(i0 + 3, im)];
                float a0 = sarea[i0];
                float a1 = sarea[min(i0 + 1, im)];
                float a2 = sarea[min(i0 + 2, im)];
                float a3 = sarea[min(i0 + 3, im)];
                for (int jb = i0 >> 5; jb < NW32; jb++) {
                    int j = (jb << 5) + lane;
                    bool v = j < n;
                    float4 bj = sbox[v ? j : 0];
                    float aj  = sarea[v ? j : 0];
                    int jgt = j - i0;
                    float ix1, iy1, ix2, iy2, inter;
                    ix1 = fmaxf(b0.x, bj.x); iy1 = fmaxf(b0.y, bj.y);
                    ix2 = fminf(b0.z, bj.z); iy2 = fminf(b0.w, bj.w);
                    inter = fmaxf(ix2 - ix1, 0.0f) * fmaxf(iy2 - iy1, 0.0f);
                    unsigned m0 = __ballot_sync(FULLM,
                        v && (jgt > 0) && (inter > 0.5f * (a0 + aj - inter)));
                    ix1 = fmaxf(b1.x, bj.x); iy1 = fmaxf(b1.y, bj.y);
                    ix2 = fminf(b1.z, bj.z); iy2 = fminf(b1.w, bj.w);
                    inter = fmaxf(ix2 - ix1, 0.0f) * fmaxf(iy2 - iy1, 0.0f);
                    unsigned m1 = __ballot_sync(FULLM,
                        v && (jgt > 1) && (inter > 0.5f * (a1 + aj - inter)));
                    ix1 = fmaxf(b2.x, bj.x); iy1 = fmaxf(b2.y, bj.y);
                    ix2 = fminf(b2.z, bj.z); iy2 = fminf(b2.w, bj.w);
                    inter = fmaxf(ix2 - ix1, 0.0f) * fmaxf(iy2 - iy1, 0.0f);
                    unsigned m2 = __ballot_sync(FULLM,
                        v && (jgt > 2) && (inter > 0.5f * (a2 + aj - inter)));
                    ix1 = fmaxf(b3.x, bj.x); iy1 = fmaxf(b3.y, bj.y);
                    ix2 = fminf(b3.z, bj.z); iy2 = fminf(b3.w, bj.w);
                    inter = fmaxf(ix2 - ix1, 0.0f) * fmaxf(iy2 - iy1, 0.0f);
                    unsigned m3 = __ballot_sync(FULLM,
                        v && (jgt > 3) && (inter > 0.5f * (a3 + aj - inter)));
                    if (lane < 4 && i0 + lane < n) {
                        unsigned mv =
                            (lane == 0) ? m0 : (lane == 1) ? m1 : (lane == 2) ? m2 : m3;
                        mrow[(i0 + lane) * MW + jb] = mv;
                    }
                }
            }
            __syncthreads();

            // ---- greedy scan, warp 0, dead-words in registers ----
            if (wid == 0) {
                unsigned dead = 0;    // lane L owns dead word L
                int ns = 0;
                for (int i = 0; i < n && ns < NDET; i++) {
                    unsigned dw = __shfl_sync(FULLM, dead, i >> 5);
                    if (!((dw >> (i & 31)) & 1u)) {
                        if (lane == 0) surv[ns] = (unsigned short)i;
                        ns++;
                        if (lane < NW32 && lane >= (i >> 5))
                            dead |= mrow[i * MW + lane];
                    }
                }
                if (lane == 0) {
                    nsurv_s = ns;
                    sbase_s = atomicAdd(&g_svcnt[b], ns);
                }
            }
        } else {
            // ---- maskless warp-greedy mid path (320 < n <= 512) ----
            for (int i = tid; i < n; i += 256) alive[i] = 1;
            __syncthreads();
            if (wid == 0) {
                int ns = 0;
                for (int i = 0; i < n && ns < NDET; i++) {
                    if (alive[i] == 0) continue;
                    if (lane == 0) surv[ns] = (unsigned short)i;
                    ns++;
                    float4 bi = sbox[i];
                    float ai = sarea[i];
                    for (int j = i + 1 + lane; j < n; j += 32) {
                        if (!alive[j]) continue;
                        float4 bj = sbox[j];
                        float ix1 = fmaxf(bi.x, bj.x), iy1 = fmaxf(bi.y, bj.y);
                        float ix2 = fminf(bi.z, bj.z), iy2 = fminf(bi.w, bj.w);
                        float inter = fmaxf(ix2 - ix1, 0.0f) * fmaxf(iy2 - iy1, 0.0f);
                        if (inter > 0.5f * (ai + sarea[j] - inter)) alive[j] = 0;
                    }
                    __syncwarp();
                }
                if (lane == 0) {
                    nsurv_s = ns;
                    sbase_s = atomicAdd(&g_svcnt[b], ns);
                }
            }
        }
        __syncthreads();

        const int so = b * SV_PER_IMG + sbase_s;
        for (int s = tid; s < nsurv_s; s += 256) {
            int i = surv[s];
            unsigned kb = (unsigned)(ssort[i] >> 32);
            g_svbox[so + s] = sbox[i];
            g_svsc[so + s]  = __uint_as_float(kb);
            g_svlab[so + s] = (unsigned char)c;
            atomicAdd(&g_hist[b * HBINS + score_bkt(kb)], 1);
        }
    } else {
        // ---- global argmax fallback (n > 512; essentially never) ----
        const float Hf = load_dim(ph);
        const float Wf = load_dim(pw);
        const float off = fmaxf(Hf, Wf) + 1.0f;
        const float t = (float)c * off;
        for (int it = 0; it < NDET; it++) {
            float bv = -2e9f; int bi = 0;
            for (int j = tid; j < n; j += 256) {
                float v = g_cs[base + j];
                if (v > bv) { bv = v; bi = j; }
            }
            #pragma unroll
            for (int o = 16; o; o >>= 1) {
                float ov = __shfl_xor_sync(FULLM, bv, o);
                int   oi = __shfl_xor_sync(FULLM, bi, o);
                if (ov > bv || (ov == bv && oi < bi)) { bv = ov; bi = oi; }
            }
            if (lane == 0) { red_v[wid] = bv; red_i[wid] = bi; }
            __syncthreads();
            if (tid == 0) {
                for (int wv = 1; wv < 8; wv++)
                    if (red_v[wv] > red_v[0] ||
                        (red_v[wv] == red_v[0] && red_i[wv] < red_i[0])) {
                        red_v[0] = red_v[wv]; red_i[0] = red_i[wv];
                    }
                if (red_v[0] < -5e8f) stop_s = 1;
                else {
                    stop_s = 0; seli_s = red_i[0];
                    selbox_s = g_cbox[base + red_i[0]];
                    gsc_s = red_v[0];
                }
            }
            __syncthreads();
            if (stop_s) break;
            float4 bx = selbox_s;
            float ox1 = bx.x + t, oy1 = bx.y + t, ox2 = bx.z + t, oy2 = bx.w + t;
            float ai = (ox2 - ox1) * (oy2 - oy1);
            for (int j = tid; j < n; j += 256) {
                float v = g_cs[base + j];
                if (v < -5e8f) continue;
                float4 bj = g_cbox[base + j];
                float jx1 = bj.x + t, jy1 = bj.y + t, jx2 = bj.z + t, jy2 = bj.w + t;
                float ix1 = fmaxf(ox1, jx1), iy1 = fmaxf(oy1, jy1);
                float ix2 = fminf(ox2, jx2), iy2 = fminf(oy2, jy2);
                float inter = fmaxf(ix2 - ix1, 0.0f) * fmaxf(iy2 - iy1, 0.0f);
                float aj = (jx2 - jx1) * (jy2 - jy1);
                if (inter > 0.5f * (ai + aj - inter)) g_cs[base + j] = NEGV;
            }
            __syncthreads();
            if (tid == 0) {
                g_cs[base + seli_s] = NEGV;
                int slot = atomicAdd(&g_svcnt[b], 1);
                g_svbox[b * SV_PER_IMG + slot] = selbox_s;
                g_svsc[b * SV_PER_IMG + slot]  = gsc_s;
                g_svlab[b * SV_PER_IMG + slot] = (unsigned char)c;
                atomicAdd(&g_hist[b * HBINS + score_bkt(__float_as_uint(gsc_s))], 1);
            }
            __syncthreads();
        }
    }
    __syncthreads();
    if (tid == 0) g_ccnt[bc] = 0;   // self-reset for next graph replay
}

// ---------------------------------------------------------------------------
// Phase C: one block per image, 1024 threads. Precomputed histogram ->
// hierarchical suffix sum -> pivot -> gather -> rank sort -> emit.
// ---------------------------------------------------------------------------
__global__ void __launch_bounds__(1024)
topk_kernel(float* __restrict__ out) {
    const int b   = blockIdx.x;
    const int tid = threadIdx.x;
    const int wid = tid >> 5;
    const int lane = tid & 31;
    const int n   = g_svcnt[b];
    const int base = b * SV_PER_IMG;
    const int nsel = (n < NDET) ? n : NDET;

    __shared__ int hist[HBINS];
    __shared__ int chunksum[32];
    __shared__ int chunksuf[32];
    __shared__ unsigned long long keys[GCAP];
    __shared__ unsigned long long skeys[GCAP];
    __shared__ int gcnt_s, pb_s;

    for (int i = tid; i < HBINS; i += 1024) {
        hist[i] = g_hist[b * HBINS + i];
        g_hist[b * HBINS + i] = 0;
    }
    if (tid == 0) { gcnt_s = 0; pb_s = 0; }
    __syncthreads();

    // hierarchical suffix sum over 2048 bins: 32 warps x 64 bins (2 bins/lane)
    int h0 = hist[(wid << 6) + (lane << 1)];
    int h1 = hist[(wid << 6) + (lane << 1) + 1];
    int acc = h0 + h1;
    #pragma unroll
    for (int o = 1; o < 32; o <<= 1) {
        int v = __shfl_down_sync(FULLM, acc, o);
        if (lane + o < 32) acc += v;
    }
    if (lane == 0) chunksum[wid] = acc;
    __syncthreads();
    if (wid == 0) {
        int cs = chunksum[lane];
        int a2 = cs;
        #pragma unroll
        for (int o = 1; o < 32; o <<= 1) {
            int v = __shfl_down_sync(FULLM, a2, o);
            if (lane + o < 32) a2 += v;
        }
        chunksuf[lane] = a2 - cs;
    }
    __syncthreads();
    {
        int above = chunksuf[wid];
        hist[(wid << 6) + (lane << 1)]     = above + acc;
        hist[(wid << 6) + (lane << 1) + 1] = above + acc - h0;
    }
    __syncthreads();

    if (nsel > 0) {
        for (int i = tid; i < HBINS; i += 1024) {
            int s = hist[i];
            int sn = (i + 1 < HBINS) ? hist[i + 1] : 0;
            if (s >= nsel && sn < nsel) pb_s = i;
        }
    }
    __syncthreads();
    const int pb = pb_s;
    const int m  = (nsel > 0) ? hist[pb] : 0;

    if (m <= GCAP) {
        for (int j = tid; j < n; j += 1024) {
            unsigned k = __float_as_uint(g_svsc[base + j]);
            if (score_bkt(k) >= pb) {
                int slot = atomicAdd(&gcnt_s, 1);
                keys[slot] = ((unsigned long long)k << 32) | (unsigned)(~j);
            }
        }
        __syncthreads();
        for (int i = tid; i < m; i += 1024) {
            unsigned long long ki = keys[i];
            int r = 0;
            for (int j = 0; j < m; j++) r += (keys[j] > ki);
            skeys[r] = ki;
        }
        __syncthreads();
    } else {
        __shared__ float red_v[32];
        __shared__ int   red_i[32];
        for (int it = 0; it < nsel; it++) {
            float bv = -2e9f; int bi = 0;
            for (int j = tid; j < n; j += 1024) {
                float v = g_svsc[base + j];
                if (v > bv) { bv = v; bi = j; }
            }
            #pragma unroll
            for (int o = 16; o; o >>= 1) {
                float ov = __shfl_xor_sync(FULLM, bv, o);
                int   oi = __shfl_xor_sync(FULLM, bi, o);
                if (ov > bv || (ov == bv && oi < bi)) { bv = ov; bi = oi; }
            }
            if (lane == 0) { red_v[wid] = bv; red_i[wid] = bi; }
            __syncthreads();
            if (tid == 0) {
                for (int wv = 1; wv < 32; wv++)
                    if (red_v[wv] > red_v[0] ||
                        (red_v[wv] == red_v[0] && red_i[wv] < red_i[0])) {
                        red_v[0] = red_v[wv]; red_i[0] = red_i[wv];
                    }
                int bsel = red_i[0];
                skeys[it] = ((unsigned long long)__float_as_uint(red_v[0]) << 32)
                          | (unsigned)(~bsel);
                g_svsc[base + bsel] = NEGV;
            }
            __syncthreads();
        }
    }

    // emit: [boxes 8*100*4][scores 8*100][labels 8*100][keep 8*100]
    const int SC0 = B_IMG * NDET * 4;
    const int LB0 = SC0 + B_IMG * NDET;
    const int KP0 = LB0 + B_IMG * NDET;
    for (int i = tid; i < NDET; i += 1024) {
        float4 bx = make_float4(0.f, 0.f, 0.f, 0.f);
        float sc = 0.0f, lb = 0.0f, kp = 0.0f;
        if (i < nsel) {
            unsigned long long kk = skeys[i];
            int j = (int)(~(unsigned)kk);
            bx = g_svbox[base + j];
            sc = __uint_as_float((unsigned)(kk >> 32));
            lb = (float)g_svlab[base + j];
            kp = 1.0f;
        }
        float* ob = out + ((size_t)b * NDET + i) * 4;
        ob[0] = bx.x; ob[1] = bx.y; ob[2] = bx.z; ob[3] = bx.w;
        out[SC0 + b * NDET + i] = sc;
        out[LB0 + b * NDET + i] = lb;
        out[KP0 + b * NDET + i] = kp;
    }
    if (tid == 0) g_svcnt[b] = 0;   // self-reset for next graph replay
}

extern "C" void kernel_launch(void* const* d_in, const int* in_sizes, int n_in,
                              void* d_out, int out_size) {
    const float* logits = (const float*)d_in[0];
    const float* reg    = (const float*)d_in[1];
    const float* props  = (const float*)d_in[2];
    const int*   ih     = (const int*)d_in[3];
    const int*   iw     = (const int*)d_in[4];
    float* out = (float*)d_out;

    phaseAB_kernel<<<NBLKA, 256>>>(logits, reg, props, ih, iw);
    class_nms_kernel<<<dim3(NCM1, B_IMG), 256>>>(ih, iw);
    topk_kernel<<<B_IMG, 1024>>>(out);
}

// round 15
// speedup vs baseline: 2.0061x; 1.6183x over previous
#include <cuda_runtime.h>
#include <cstdint>
#include <math.h>

#define B_IMG 8
#define NPROP 4000
#define NCLS 91
#define NCM1 90
#define CAPC 4000                    // worst-case candidates per (image,class)
#define NDET 100
#define NEGV -1e9f
#define CAPSM 512                    // smem sort cap for class NMS
#define MASKN 320                    // mask-path cap
#define MW 10                        // u32 mask words per row (MASKN/32)
#define SV_PER_IMG (NCM1 * NDET)     // 9000 survivors per image (capped)
#define GCAP 1024                    // topk gather capacity
#define HBINS 2048
#define HLO 30720                    // (key>>15) offset; covers scores >~0.0078
#define NBLKA 2000                   // phaseAB blocks (16 proposals each)
#define QCAP 320                     // smem queue cap (<=20 passers/proposal)
#define FULLM 0xffffffffu

static __device__ float4        g_cbox[B_IMG * NCM1 * CAPC];
static __device__ float         g_cs[B_IMG * NCM1 * CAPC];
static __device__ int           g_ccnt[B_IMG * NCM1];    // zero-init, self-reset
static __device__ float4        g_svbox[B_IMG * SV_PER_IMG];
static __device__ float         g_svsc[B_IMG * SV_PER_IMG];
static __device__ unsigned char g_svlab[B_IMG * SV_PER_IMG];
static __device__ int           g_svcnt[B_IMG];          // zero-init, self-reset
static __device__ int           g_hist[B_IMG * HBINS];   // zero-init, topk re-zeros
static __device__ float         g_T[B_IMG];              // overwritten each replay

__device__ __forceinline__ float load_dim(const int* p) {
    int vi = *p;
    if (vi > 0 && vi < 1000000) return (float)vi;
    return __int_as_float(vi);
}

__device__ __forceinline__ int score_bkt(unsigned keybits) {
    int bkt = (int)(keybits >> 15) - HLO;
    return max(0, min(HBINS - 1, bkt));
}

// ---------------------------------------------------------------------------
// Phase AB (fused): softmax + threshold filter -> smem queue -> dense decode.
// (unchanged — measured ~20us)
// ---------------------------------------------------------------------------
__global__ void __launch_bounds__(256)
phaseAB_kernel(const float* __restrict__ logits,
               const float* __restrict__ reg,
               const float* __restrict__ props,
               const int* __restrict__ ph,
               const int* __restrict__ pw) {
    const int warp = threadIdx.x >> 5;
    const int lane = threadIdx.x & 31;
    const int p0 = (blockIdx.x * 8 + warp) << 1;

    __shared__ unsigned long long q[QCAP];
    __shared__ int s_cnt;
    if (threadIdx.x == 0) s_cnt = 0;
    __syncthreads();

    const float* z0 = logits + (size_t)p0 * NCLS;
    const float* z1 = z0 + NCLS;

    float e[2][3];
    e[0][0] = __expf(z0[lane]);
    e[1][0] = __expf(z1[lane]);
    e[0][1] = __expf(z0[lane + 32]);
    e[1][1] = __expf(z1[lane + 32]);
    e[0][2] = (lane < NCLS - 64) ? __expf(z0[lane + 64]) : 0.0f;
    e[1][2] = (lane < NCLS - 64) ? __expf(z1[lane + 64]) : 0.0f;

    float ssum[2];
    ssum[0] = e[0][0] + e[0][1] + e[0][2];
    ssum[1] = e[1][0] + e[1][1] + e[1][2];
    #pragma unroll
    for (int o = 16; o; o >>= 1) {
        ssum[0] += __shfl_xor_sync(FULLM, ssum[0], o);
        ssum[1] += __shfl_xor_sync(FULLM, ssum[1], o);
    }

    bool pass[6];
    int cnt = 0;
    #pragma unroll
    for (int k = 0; k < 2; k++) {
        float thr = 0.05f * ssum[k];
        #pragma unroll
        for (int t = 0; t < 3; t++) {
            int c = lane + 32 * t;
            bool pk = (c > 0) && (c < NCLS) && (e[k][t] > thr);
            pass[k * 3 + t] = pk;
            cnt += pk ? 1 : 0;
        }
    }

    int incl = cnt;
    #pragma unroll
    for (int o = 1; o < 32; o <<= 1) {
        int v = __shfl_up_sync(FULLM, incl, o);
        if (lane >= o) incl += v;
    }
    int total = __shfl_sync(FULLM, incl, 31);
    int wbase = 0;
    if (total > 0) {
        if (lane == 31) wbase = atomicAdd(&s_cnt, total);
        wbase = __shfl_sync(FULLM, wbase, 31);
        int off = wbase + incl - cnt;
        #pragma unroll
        for (int k = 0; k < 2; k++) {
            #pragma unroll
            for (int t = 0; t < 3; t++) {
                if (pass[k * 3 + t]) {
                    int c = lane + 32 * t;
                    float sc = e[k][t] / ssum[k];
                    unsigned idx = ((unsigned)(p0 + k) << 7) | (unsigned)c;
                    q[off++] = ((unsigned long long)__float_as_uint(sc) << 32) | idx;
                }
            }
        }
    }
    __syncthreads();

    const int qcnt = s_cnt;
    const float Wf = load_dim(pw);
    const float Hf = load_dim(ph);
    const float CLIPV = 4.135166556742356f;  // log(1000/16)

    for (int i = threadIdx.x; i < qcnt; i += 256) {
        unsigned long long en = q[i];
        float sc = __uint_as_float((unsigned)(en >> 32));
        unsigned idx = (unsigned)en;
        int p = idx >> 7, c = idx & 127;

        float4 pr = ((const float4*)props)[p];
        float w = pr.z - pr.x, h = pr.w - pr.y;
        float cx = pr.x + 0.5f * w, cy = pr.y + 0.5f * h;
        float4 r = ((const float4*)reg)[p * NCLS + c];

        float dx = r.x / 10.0f, dy = r.y / 10.0f;
        float dw = fminf(r.z / 5.0f, CLIPV);
        float dh = fminf(r.w / 5.0f, CLIPV);
        float pcx = dx * w + cx, pcy = dy * h + cy;
        float pwd = __expf(dw) * w, phd = __expf(dh) * h;
        float x1 = pcx - 0.5f * pwd, y1 = pcy - 0.5f * phd;
        float x2 = pcx + 0.5f * pwd, y2 = pcy + 0.5f * phd;
        x1 = fminf(fmaxf(x1, 0.0f), Wf); x2 = fminf(fmaxf(x2, 0.0f), Wf);
        y1 = fminf(fmaxf(y1, 0.0f), Hf); y2 = fminf(fmaxf(y2, 0.0f), Hf);
        if ((x2 - x1) >= 0.01f && (y2 - y1) >= 0.01f) {
            int b = p / NPROP;
            int bc = b * NCM1 + (c - 1);
            int pos = atomicAdd(&g_ccnt[bc], 1);
            size_t o = (size_t)bc * CAPC + pos;
            g_cbox[o] = make_float4(x1, y1, x2, y2);
            g_cs[o]   = sc;
        }
    }
}

// ---------------------------------------------------------------------------
// Threshold kernel: one block per image. For each class: top survivor score
// (class max) and 2nd survivor score (best non-overlapping with the max) —
// both PROVABLY greedy-NMS survivors. T = 100th largest of these 180 values
// (0 if fewer than 100). Candidates with score < T are provably irrelevant.
// ---------------------------------------------------------------------------
__global__ void __launch_bounds__(1024)
thresh_kernel(void) {
    const int b = blockIdx.x;
    const int tid = threadIdx.x;
    const int wid = tid >> 5;
    const int lane = tid & 31;

    __shared__ unsigned long long vals[192];
    __shared__ float T_s;
    for (int i = tid; i < 192; i += 1024) vals[i] = 0ull;
    if (tid == 0) T_s = 0.0f;
    __syncthreads();

    for (int t = wid; t < NCM1; t += 32) {
        const int bc = b * NCM1 + t;
        const int n = g_ccnt[bc];
        if (n == 0) continue;               // n uniform across warp
        const size_t base = (size_t)bc * CAPC;

        float m1 = -2e9f; int i1 = 0x7fffffff;
        for (int j = lane; j < n; j += 32) {
            float s = g_cs[base + j];
            if (s > m1) { m1 = s; i1 = j; }
        }
        #pragma unroll
        for (int o = 16; o; o >>= 1) {
            float ov = __shfl_xor_sync(FULLM, m1, o);
            int   oi = __shfl_xor_sync(FULLM, i1, o);
            if (ov > m1 || (ov == m1 && oi < i1)) { m1 = ov; i1 = oi; }
        }

        float4 b1 = g_cbox[base + i1];
        float a1 = (b1.z - b1.x) * (b1.w - b1.y);
        float m2 = -2e9f;
        for (int j = lane; j < n; j += 32) {
            if (j == i1) continue;
            float s = g_cs[base + j];
            if (s <= m2) continue;
            float4 bj = g_cbox[base + j];
            float ix1 = fmaxf(b1.x, bj.x), iy1 = fmaxf(b1.y, bj.y);
            float ix2 = fminf(b1.z, bj.z), iy2 = fminf(b1.w, bj.w);
            float inter = fmaxf(ix2 - ix1, 0.0f) * fmaxf(iy2 - iy1, 0.0f);
            float aj = (bj.z - bj.x) * (bj.w - bj.y);
            if (!(inter > 0.5f * (a1 + aj - inter))) m2 = s;   // survives round 1
        }
        #pragma unroll
        for (int o = 16; o; o >>= 1)
            m2 = fmaxf(m2, __shfl_xor_sync(FULLM, m2, o));

        if (lane == 0) {
            vals[2 * t] = ((unsigned long long)__float_as_uint(m1) << 32)
                        | (unsigned)(2 * t);
            if (m2 > 0.0f)
                vals[2 * t + 1] = ((unsigned long long)__float_as_uint(m2) << 32)
                                | (unsigned)(2 * t + 1);
        }
    }
    __syncthreads();

    // 100th largest of the (unique, nonzero) keys; zero keys rank below all
    if (tid < 192) {
        unsigned long long ki = vals[tid];
        if (ki != 0ull) {
            int r = 0;
            for (int j = 0; j < 192; j++) r += (vals[j] > ki);
            if (r == 99) T_s = __uint_as_float((unsigned)(ki >> 32));
        }
    }
    __syncthreads();
    if (tid == 0) g_T[b] = T_s;
}

// ---------------------------------------------------------------------------
// Phase B: one block per (image,class). PRUNE to score >= T[b] (exact), then
// x4-row ballot rank sort + x4-row ballot mask build + warp-0 register greedy
// scan. Survivors + per-image histogram to global.
// ---------------------------------------------------------------------------
__global__ void __launch_bounds__(256, 5)
class_nms_kernel(const int* __restrict__ ph, const int* __restrict__ pw) {
    const int c  = blockIdx.x + 1;
    const int b  = blockIdx.y;
    const int bc = b * NCM1 + (c - 1);
    const int tid = threadIdx.x;
    const int wid = tid >> 5;
    const int lane = tid & 31;
    const int n = g_ccnt[bc];
    if (n == 0) return;

    __shared__ unsigned long long skey[CAPSM];
    __shared__ unsigned long long ssort[CAPSM];
    __shared__ float4             sbox[CAPSM];
    __shared__ float              sarea[CAPSM];
    __shared__ unsigned int       mrow[MASKN * MW];
    __shared__ unsigned char      alive[CAPSM];
    __shared__ unsigned short     surv[NDET];
    __shared__ int                nsurv_s, sbase_s, cn_s;
    __shared__ float              red_v[8];
    __shared__ int                red_i[8];
    __shared__ int                stop_s, seli_s;
    __shared__ float4             selbox_s;
    __shared__ float              gsc_s;

    const size_t base = (size_t)bc * CAPC;

    if (n <= CAPSM) {
        // ---- prune + compact (score >= T is exact; see thresh_kernel) ----
        const float T = g_T[b];
        if (tid == 0) cn_s = 0;
        __syncthreads();
        for (int j = tid; j < n; j += 256) {
            float s = g_cs[base + j];
            if (s >= T) {
                int p = atomicAdd(&cn_s, 1);
                skey[p] = ((unsigned long long)__float_as_uint(s) << 32)
                        | (unsigned)j;
            }
        }
        __syncthreads();
        const int n2 = cn_s;

        if (n2 > 0) {
        const int NW32 = (n2 + 31) >> 5;
        const int im = n2 - 1;

        // x4-row ballot rank sort
        for (int i0 = wid << 2; i0 < n2; i0 += 32) {
            unsigned long long k0 = skey[i0];
            unsigned long long k1 = skey[min(i0 + 1, im)];
            unsigned long long k2 = skey[min(i0 + 2, im)];
            unsigned long long k3 = skey[min(i0 + 3, im)];
            int r0 = 0, r1 = 0, r2 = 0, r3 = 0;
            for (int jb = 0; jb < NW32; jb++) {
                int j = (jb << 5) + lane;
                bool v = j < n2;
                unsigned long long kj = skey[v ? j : 0];
                r0 += __popc(__ballot_sync(FULLM, v && (kj > k0)));
                r1 += __popc(__ballot_sync(FULLM, v && (kj > k1)));
                r2 += __popc(__ballot_sync(FULLM, v && (kj > k2)));
                r3 += __popc(__ballot_sync(FULLM, v && (kj > k3)));
            }
            if (lane < 4 && i0 + lane < n2) {
                int rr = (lane == 0) ? r0 : (lane == 1) ? r1 : (lane == 2) ? r2 : r3;
                unsigned long long kk =
                    (lane == 0) ? k0 : (lane == 1) ? k1 : (lane == 2) ? k2 : k3;
                ssort[rr] = kk;
            }
        }
        __syncthreads();

        for (int i = tid; i < n2; i += 256) {
            float4 bx = g_cbox[base + (unsigned)(ssort[i] & 0xffffffffu)];
            sbox[i]  = bx;
            sarea[i] = (bx.z - bx.x) * (bx.w - bx.y);
        }
        __syncthreads();

        if (n2 <= MASKN) {
            // ---- x4-row ballot mask build ----
            for (int i0 = wid << 2; i0 < n2; i0 += 32) {
                float4 b0 = sbox[i0];
                float4 b1 = sbox[min(i0 + 1, im)];
                float4 b2 = sbox[min(i0 + 2, im)];
                float4 b3 = sbox[min(i0 + 3, im)];
                float a0 = sarea[i0];
                float a1 = sarea[min(i0 + 1, im)];
                float a2 = sarea[min(i0 + 2, im)];
                float a3 = sarea[min(i0 + 3, im)];
                for (int jb = i0 >> 5; jb < NW32; jb++) {
                    int j = (jb << 5) + lane;
                    bool v = j < n2;
                    float4 bj = sbox[v ? j : 0];
                    float aj  = sarea[v ? j : 0];
                    int jgt = j - i0;
                    float ix1, iy1, ix2, iy2, inter;
                    ix1 = fmaxf(b0.x, bj.x); iy1 = fmaxf(b0.y, bj.y);
                    ix2 = fminf(b0.z, bj.z); iy2 = fminf(b0.w, bj.w);
                    inter = fmaxf(ix2 - ix1, 0.0f) * fmaxf(iy2 - iy1, 0.0f);
                    unsigned m0 = __ballot_sync(FULLM,
                        v && (jgt > 0) && (inter > 0.5f * (a0 + aj - inter)));
                    ix1 = fmaxf(b1.x, bj.x); iy1 = fmaxf(b1.y, bj.y);
                    ix2 = fminf(b1.z, bj.z); iy2 = fminf(b1.w, bj.w);
                    inter = fmaxf(ix2 - ix1, 0.0f) * fmaxf(iy2 - iy1, 0.0f);
                    unsigned m1 = __ballot_sync(FULLM,
                        v && (jgt > 1) && (inter > 0.5f * (a1 + aj - inter)));
                    ix1 = fmaxf(b2.x, bj.x); iy1 = fmaxf(b2.y, bj.y);
                    ix2 = fminf(b2.z, bj.z); iy2 = fminf(b2.w, bj.w);
                    inter = fmaxf(ix2 - ix1, 0.0f) * fmaxf(iy2 - iy1, 0.0f);
                    unsigned m2 = __ballot_sync(FULLM,
                        v && (jgt > 2) && (inter > 0.5f * (a2 + aj - inter)));
                    ix1 = fmaxf(b3.x, bj.x); iy1 = fmaxf(b3.y, bj.y);
                    ix2 = fminf(b3.z, bj.z); iy2 = fminf(b3.w, bj.w);
                    inter = fmaxf(ix2 - ix1, 0.0f) * fmaxf(iy2 - iy1, 0.0f);
                    unsigned m3 = __ballot_sync(FULLM,
                        v && (jgt > 3) && (inter > 0.5f * (a3 + aj - inter)));
                    if (lane < 4 && i0 + lane < n2) {
                        unsigned mv =
                            (lane == 0) ? m0 : (lane == 1) ? m1 : (lane == 2) ? m2 : m3;
                        mrow[(i0 + lane) * MW + jb] = mv;
                    }
                }
            }
            __syncthreads();

            // ---- greedy scan, warp 0, dead-words in registers ----
            if (wid == 0) {
                unsigned dead = 0;    // lane L owns dead word L
                int ns = 0;
                for (int i = 0; i < n2 && ns < NDET; i++) {
                    unsigned dw = __shfl_sync(FULLM, dead, i >> 5);
                    if (!((dw >> (i & 31)) & 1u)) {
                        if (lane == 0) surv[ns] = (unsigned short)i;
                        ns++;
                        if (lane < NW32 && lane >= (i >> 5))
                            dead |= mrow[i * MW + lane];
                    }
                }
                if (lane == 0) {
                    nsurv_s = ns;
                    sbase_s = atomicAdd(&g_svcnt[b], ns);
                }
            }
        } else {
            // ---- maskless warp-greedy mid path (MASKN < n2 <= CAPSM) ----
            for (int i = tid; i < n2; i += 256) alive[i] = 1;
            __syncthreads();
            if (wid == 0) {
                int ns = 0;
                for (int i = 0; i < n2 && ns < NDET; i++) {
                    if (alive[i] == 0) continue;
                    if (lane == 0) surv[ns] = (unsigned short)i;
                    ns++;
                    float4 bi = sbox[i];
                    float ai = sarea[i];
                    for (int j = i + 1 + lane; j < n2; j += 32) {
                        if (!alive[j]) continue;
                        float4 bj = sbox[j];
                        float ix1 = fmaxf(bi.x, bj.x), iy1 = fmaxf(bi.y, bj.y);
                        float ix2 = fminf(bi.z, bj.z), iy2 = fminf(bi.w, bj.w);
                        float inter = fmaxf(ix2 - ix1, 0.0f) * fmaxf(iy2 - iy1, 0.0f);
                        if (inter > 0.5f * (ai + sarea[j] - inter)) alive[j] = 0;
                    }
                    __syncwarp();
                }
                if (lane == 0) {
                    nsurv_s = ns;
                    sbase_s = atomicAdd(&g_svcnt[b], ns);
                }
            }
        }
        __syncthreads();

        const int so = b * SV_PER_IMG + sbase_s;
        for (int s = tid; s < nsurv_s; s += 256) {
            int i = surv[s];
            unsigned kb = (unsigned)(ssort[i] >> 32);
            g_svbox[so + s] = sbox[i];
            g_svsc[so + s]  = __uint_as_float(kb);
            g_svlab[so + s] = (unsigned char)c;
            atomicAdd(&g_hist[b * HBINS + score_bkt(kb)], 1);
        }
        }  // n2 > 0
    } else {
        // ---- global argmax fallback (n > 512; essentially never) ----
        const float Hf = load_dim(ph);
        const float Wf = load_dim(pw);
        const float off = fmaxf(Hf, Wf) + 1.0f;
        const float t = (float)c * off;
        for (int it = 0; it < NDET; it++) {
            float bv = -2e9f; int bi = 0;
            for (int j = tid; j < n; j += 256) {
                float v = g_cs[base + j];
                if (v > bv) { bv = v; bi = j; }
            }
            #pragma unroll
            for (int o = 16; o; o >>= 1) {
                float ov = __shfl_xor_sync(FULLM, bv, o);
                int   oi = __shfl_xor_sync(FULLM, bi, o);
                if (ov > bv || (ov == bv && oi < bi)) { bv = ov; bi = oi; }
            }
            if (lane == 0) { red_v[wid] = bv; red_i[wid] = bi; }
            __syncthreads();
            if (tid == 0) {
                for (int wv = 1; wv < 8; wv++)
                    if (red_v[wv] > red_v[0] ||
                        (red_v[wv] == red_v[0] && red_i[wv] < red_i[0])) {
                        red_v[0] = red_v[wv]; red_i[0] = red_i[wv];
                    }
                if (red_v[0] < -5e8f) stop_s = 1;
                else {
                    stop_s = 0; seli_s = red_i[0];
                    selbox_s = g_cbox[base + red_i[0]];
                    gsc_s = red_v[0];
                }
            }
            __syncthreads();
            if (stop_s) break;
            float4 bx = selbox_s;
            float ox1 = bx.x + t, oy1 = bx.y + t, ox2 = bx.z + t, oy2 = bx.w + t;
            float ai = (ox2 - ox1) * (oy2 - oy1);
            for (int j = tid; j < n; j += 256) {
                float v = g_cs[base + j];
                if (v < -5e8f) continue;
                float4 bj = g_cbox[base + j];
                float jx1 = bj.x + t, jy1 = bj.y + t, jx2 = bj.z + t, jy2 = bj.w + t;
                float ix1 = fmaxf(ox1, jx1), iy1 = fmaxf(oy1, jy1);
                float ix2 = fminf(ox2, jx2), iy2 = fminf(oy2, jy2);
                float inter = fmaxf(ix2 - ix1, 0.0f) * fmaxf(iy2 - iy1, 0.0f);
                float aj = (jx2 - jx1) * (jy2 - jy1);
                if (inter > 0.5f * (ai + aj - inter)) g_cs[base + j] = NEGV;
            }
            __syncthreads();
            if (tid == 0) {
                g_cs[base + seli_s] = NEGV;
                int slot = atomicAdd(&g_svcnt[b], 1);
                g_svbox[b * SV_PER_IMG + slot] = selbox_s;
                g_svsc[b * SV_PER_IMG + slot]  = gsc_s;
                g_svlab[b * SV_PER_IMG + slot] = (unsigned char)c;
                atomicAdd(&g_hist[b * HBINS + score_bkt(__float_as_uint(gsc_s))], 1);
            }
            __syncthreads();
        }
    }
    __syncthreads();
    if (tid == 0) g_ccnt[bc] = 0;   // self-reset for next graph replay
}

// ---------------------------------------------------------------------------
// Phase C: one block per image, 1024 threads. Precomputed histogram ->
// hierarchical suffix sum -> pivot -> gather -> rank sort -> emit.
// ---------------------------------------------------------------------------
__global__ void __launch_bounds__(1024)
topk_kernel(float* __restrict__ out) {
    const int b   = blockIdx.x;
    const int tid = threadIdx.x;
    const int wid = tid >> 5;
    const int lane = tid & 31;
    const int n   = g_svcnt[b];
    const int base = b * SV_PER_IMG;
    const int nsel = (n < NDET) ? n : NDET;

    __shared__ int hist[HBINS];
    __shared__ int chunksum[32];
    __shared__ int chunksuf[32];
    __shared__ unsigned long long keys[GCAP];
    __shared__ unsigned long long skeys[GCAP];
    __shared__ int gcnt_s, pb_s;

    for (int i = tid; i < HBINS; i += 1024) {
        hist[i] = g_hist[b * HBINS + i];
        g_hist[b * HBINS + i] = 0;
    }
    if (tid == 0) { gcnt_s = 0; pb_s = 0; }
    __syncthreads();

    int h0 = hist[(wid << 6) + (lane << 1)];
    int h1 = hist[(wid << 6) + (lane << 1) + 1];
    int acc = h0 + h1;
    #pragma unroll
    for (int o = 1; o < 32; o <<= 1) {
        int v = __shfl_down_sync(FULLM, acc, o);
        if (lane + o < 32) acc += v;
    }
    if (lane == 0) chunksum[wid] = acc;
    __syncthreads();
    if (wid == 0) {
        int cs = chunksum[lane];
        int a2 = cs;
        #pragma unroll
        for (int o = 1; o < 32; o <<= 1) {
            int v = __shfl_down_sync(FULLM, a2, o);
            if (lane + o < 32) a2 += v;
        }
        chunksuf[lane] = a2 - cs;
    }
    __syncthreads();
    {
        int above = chunksuf[wid];
        hist[(wid << 6) + (lane << 1)]     = above + acc;
        hist[(wid << 6) + (lane << 1) + 1] = above + acc - h0;
    }
    __syncthreads();

    if (nsel > 0) {
        for (int i = tid; i < HBINS; i += 1024) {
            int s = hist[i];
            int sn = (i + 1 < HBINS) ? hist[i + 1] : 0;
            if (s >= nsel && sn < nsel) pb_s = i;
        }
    }
    __syncthreads();
    const int pb = pb_s;
    const int m  = (nsel > 0) ? hist[pb] : 0;

    if (m <= GCAP) {
        for (int j = tid; j < n; j += 1024) {
            unsigned k = __float_as_uint(g_svsc[base + j]);
            if (score_bkt(k) >= pb) {
                int slot = atomicAdd(&gcnt_s, 1);
                keys[slot] = ((unsigned long long)k << 32) | (unsigned)(~j);
            }
        }
        __syncthreads();
        for (int i = tid; i < m; i += 1024) {
            unsigned long long ki = keys[i];
            int r = 0;
            for (int j = 0; j < m; j++) r += (keys[j] > ki);
            skeys[r] = ki;
        }
        __syncthreads();
    } else {
        __shared__ float red_v[32];
        __shared__ int   red_i[32];
        for (int it = 0; it < nsel; it++) {
            float bv = -2e9f; int bi = 0;
            for (int j = tid; j < n; j += 1024) {
                float v = g_svsc[base + j];
                if (v > bv) { bv = v; bi = j; }
            }
            #pragma unroll
            for (int o = 16; o; o >>= 1) {
                float ov = __shfl_xor_sync(FULLM, bv, o);
                int   oi = __shfl_xor_sync(FULLM, bi, o);
                if (ov > bv || (ov == bv && oi < bi)) { bv = ov; bi = oi; }
            }
            if (lane == 0) { red_v[wid] = bv; red_i[wid] = bi; }
            __syncthreads();
            if (tid == 0) {
                for (int wv = 1; wv < 32; wv++)
                    if (red_v[wv] > red_v[0] ||
                        (red_v[wv] == red_v[0] && red_i[wv] < red_i[0])) {
                        red_v[0] = red_v[wv]; red_i[0] = red_i[wv];
                    }
                int bsel = red_i[0];
                skeys[it] = ((unsigned long long)__float_as_uint(red_v[0]) << 32)
                          | (unsigned)(~bsel);
                g_svsc[base + bsel] = NEGV;
            }
            __syncthreads();
        }
    }

    // emit: [boxes 8*100*4][scores 8*100][labels 8*100][keep 8*100]
    const int SC0 = B_IMG * NDET * 4;
    const int LB0 = SC0 + B_IMG * NDET;
    const int KP0 = LB0 + B_IMG * NDET;
    for (int i = tid; i < NDET; i += 1024) {
        float4 bx = make_float4(0.f, 0.f, 0.f, 0.f);
        float sc = 0.0f, lb = 0.0f, kp = 0.0f;
        if (i < nsel) {
            unsigned long long kk = skeys[i];
            int j = (int)(~(unsigned)kk);
            bx = g_svbox[base + j];
            sc = __uint_as_float((unsigned)(kk >> 32));
            lb = (float)g_svlab[base + j];
            kp = 1.0f;
        }
        float* ob = out + ((size_t)b * NDET + i) * 4;
        ob[0] = bx.x; ob[1] = bx.y; ob[2] = bx.z; ob[3] = bx.w;
        out[SC0 + b * NDET + i] = sc;
        out[LB0 + b * NDET + i] = lb;
        out[KP0 + b * NDET + i] = kp;
    }
    if (tid == 0) g_svcnt[b] = 0;   // self-reset for next graph replay
}

extern "C" void kernel_launch(void* const* d_in, const int* in_sizes, int n_in,
                              void* d_out, int out_size) {
    const float* logits = (const float*)d_in[0];
    const float* reg    = (const float*)d_in[1];
    const float* props  = (const float*)d_in[2];
    const int*   ih     = (const int*)d_in[3];
    const int*   iw     = (const int*)d_in[4];
    float* out = (float*)d_out;

    phaseAB_kernel<<<NBLKA, 256>>>(logits, reg, props, ih, iw);
    thresh_kernel<<<B_IMG, 1024>>>();
    class_nms_kernel<<<dim3(NCM1, B_IMG), 256>>>(ih, iw);
    topk_kernel<<<B_IMG, 1024>>>(out);
}